// round 15
// baseline (speedup 1.0000x reference)
#include <cuda_runtime.h>
#include <cuda_bf16.h>
#include <cstdint>
#include <math.h>

// ---------------------------------------------------------------------------
// Problem constants
// ---------------------------------------------------------------------------
#define BB   2
#define SS   2048
#define DD   2048
#define HH   16
#define DK   128
#define MTOK (BB * SS)          // 4096 tokens
#define SCALE 0.08838834764831845f  // 1/sqrt(128)

// Scratch (device globals; no cudaMalloc allowed)
static __device__ float g_v [(size_t)MTOK * DD];
static __device__ float g_rpart[(size_t)BB * HH * SS * 16];
static __device__ float g_inv[(size_t)BB * HH * SS];
// bf16 hi/lo planes
static __device__ __nv_bfloat16 g_qih[(size_t)MTOK * DD], g_qil[(size_t)MTOK * DD];
static __device__ __nv_bfloat16 g_kih[(size_t)MTOK * DD], g_kil[(size_t)MTOK * DD];
static __device__ __nv_bfloat16 g_vih[(size_t)MTOK * DD], g_vil[(size_t)MTOK * DD];
static __device__ __nv_bfloat16 g_wh[(size_t)4 * DD * DD], g_wl[(size_t)4 * DD * DD];
static __device__ __nv_bfloat16 g_qh[(size_t)MTOK * DD], g_ql[(size_t)MTOK * DD];
static __device__ __nv_bfloat16 g_kh[(size_t)MTOK * DD], g_kl[(size_t)MTOK * DD];
static __device__ __nv_bfloat16 g_xh[(size_t)MTOK * DD], g_xl[(size_t)MTOK * DD];
static __device__ __nv_bfloat16 g_vth[(size_t)BB * HH * DK * SS];
static __device__ __nv_bfloat16 g_vtl[(size_t)BB * HH * DK * SS];
// Unnormalized-E planes
static __device__ __nv_bfloat16 g_eh[(size_t)BB * HH * SS * SS];
static __device__ __nv_bfloat16 g_el[(size_t)BB * HH * SS * SS];

// ---------------------------------------------------------------------------
// PTX helpers
// ---------------------------------------------------------------------------
#define LDSM_X4(r0, r1, r2, r3, addr) \
    asm volatile("ldmatrix.sync.aligned.m8n8.x4.shared.b16 {%0,%1,%2,%3}, [%4];" \
        : "=r"(r0), "=r"(r1), "=r"(r2), "=r"(r3) : "r"(addr))

#define MMA16816(c, a0, a1, a2, a3, b0, b1) \
    asm volatile("mma.sync.aligned.m16n8k16.row.col.f32.bf16.bf16.f32 " \
        "{%0,%1,%2,%3}, {%4,%5,%6,%7}, {%8,%9}, {%0,%1,%2,%3};" \
        : "+f"((c)[0]), "+f"((c)[1]), "+f"((c)[2]), "+f"((c)[3]) \
        : "r"(a0), "r"(a1), "r"(a2), "r"(a3), "r"(b0), "r"(b1))

#define CP16(dst, src) \
    asm volatile("cp.async.cg.shared.global [%0], [%1], 16;" \
        :: "r"(dst), "l"(src))
#define CPCOMMIT() asm volatile("cp.async.commit_group;" ::: "memory")
#define CPWAIT1()  asm volatile("cp.async.wait_group 1;" ::: "memory")

__device__ __forceinline__ uint32_t smem_u32(const void* p) {
    uint32_t a;
    asm("{ .reg .u64 t; cvta.to.shared.u64 t, %1; cvt.u32.u64 %0, t; }"
        : "=r"(a) : "l"(p));
    return a;
}

__device__ __forceinline__ uint32_t pack_bf2(__nv_bfloat16 a, __nv_bfloat16 b) {
    return (uint32_t)__bfloat16_as_ushort(a) |
           ((uint32_t)__bfloat16_as_ushort(b) << 16);
}

__device__ __forceinline__ void split4(const float4 f, uint2& hi, uint2& lo) {
    __nv_bfloat16 h0 = __float2bfloat16_rn(f.x);
    __nv_bfloat16 h1 = __float2bfloat16_rn(f.y);
    __nv_bfloat16 h2 = __float2bfloat16_rn(f.z);
    __nv_bfloat16 h3 = __float2bfloat16_rn(f.w);
    __nv_bfloat16 l0 = __float2bfloat16_rn(f.x - __bfloat162float(h0));
    __nv_bfloat16 l1 = __float2bfloat16_rn(f.y - __bfloat162float(h1));
    __nv_bfloat16 l2 = __float2bfloat16_rn(f.z - __bfloat162float(h2));
    __nv_bfloat16 l3 = __float2bfloat16_rn(f.w - __bfloat162float(h3));
    hi.x = pack_bf2(h0, h1); hi.y = pack_bf2(h2, h3);
    lo.x = pack_bf2(l0, l1); lo.y = pack_bf2(l2, l3);
}

// ---------------------------------------------------------------------------
// MmaB16v8: 128x128 tile, 128 threads (4 warps, 64x64 warp tile),
// K-chunk 32, 64B rows with (r>>1)&3 XOR-16B swizzle (conflict-free
// ldmatrix), NS=3 pipeline. 2 CTAs/SM, natural regs. Half the barriers of v6.
// ---------------------------------------------------------------------------
#define NS8 3
#define P8_AHI 0
#define P8_ALO 8192
#define P8_BHI 16384
#define P8_BLO 24576
#define S8_BYTES 32768
#define DSMEM_V8 (NS8 * S8_BYTES)   // 98304

struct MmaB16v8 {
    float acc[4][8][4];

    __device__ __forceinline__ static void issue(
        uint32_t sb,
        const __nv_bfloat16* Ah, const __nv_bfloat16* Al, size_t sA,
        const __nv_bfloat16* Bh, const __nv_bfloat16* Bl, size_t sB,
        int k0, int tid)
    {
        const int r = tid;                  // 0..127, one row per thread
        const uint32_t g = ((uint32_t)r >> 1) & 3;
        const uint32_t rowo = (uint32_t)r * 64;
        const size_t gA = (size_t)r * sA + k0;
        const size_t gB = (size_t)r * sB + k0;
        #pragma unroll
        for (int c = 0; c < 4; c++) {
            const uint32_t sw = rowo + (((uint32_t)c ^ g) << 4);
            CP16(sb + P8_AHI + sw, Ah + gA + c * 8);
            CP16(sb + P8_ALO + sw, Al + gA + c * 8);
            CP16(sb + P8_BHI + sw, Bh + gB + c * 8);
            CP16(sb + P8_BLO + sw, Bl + gB + c * 8);
        }
    }

    __device__ __forceinline__ void run(
        uint32_t sbase,
        const __nv_bfloat16* Ah, const __nv_bfloat16* Al, size_t sA,
        const __nv_bfloat16* Bh, const __nv_bfloat16* Bl, size_t sB,
        const int nIter, const int tid)   // nIter in K-chunks of 32
    {
        const int lane = tid & 31;
        const int wid  = tid >> 5;
        const int wm   = wid >> 1;
        const int wn   = wid & 1;

        #pragma unroll
        for (int i = 0; i < 4; i++)
            #pragma unroll
            for (int j = 0; j < 8; j++)
                #pragma unroll
                for (int c = 0; c < 4; c++) acc[i][j][c] = 0.0f;

        const uint32_t g = ((uint32_t)lane >> 1) & 3;   // == (row>>1)&3 for A and B
        const uint32_t aBase = sbase + P8_AHI
            + (uint32_t)(wm * 64 + (lane & 15)) * 64;
        const uint32_t bBase = sbase + P8_BHI
            + (uint32_t)(wn * 64 + (lane & 7) + ((lane >> 4) & 1) * 8) * 64;
        const uint32_t aCh = (uint32_t)(lane >> 4);        // logical 16B half (A)
        const uint32_t bCh = (uint32_t)((lane >> 3) & 1);  // logical 16B half (B)

        #pragma unroll
        for (int p = 0; p < NS8 - 1; p++) {
            if (p < nIter)
                issue(sbase + p * S8_BYTES, Ah, Al, sA, Bh, Bl, sB, p * 32, tid);
            CPCOMMIT();
        }

        int bufc = 0;
        for (int s = 0; s < nIter; s++) {
            CPWAIT1();
            __syncthreads();

            const uint32_t bo = (uint32_t)bufc * S8_BYTES;
            #pragma unroll
            for (int kk = 0; kk < 2; kk++) {
                const uint32_t aSw = (((uint32_t)(kk * 2) + aCh) ^ g) << 4;
                const uint32_t bSw = (((uint32_t)(kk * 2) + bCh) ^ g) << 4;
                uint32_t ahi[4][4], alo[4][4];
                uint32_t bhi[4][4], blo[4][4];
                #pragma unroll
                for (int mt = 0; mt < 4; mt++) {
                    const uint32_t a = aBase + bo + mt * (16 * 64) + aSw;
                    LDSM_X4(ahi[mt][0], ahi[mt][1], ahi[mt][2], ahi[mt][3], a);
                    LDSM_X4(alo[mt][0], alo[mt][1], alo[mt][2], alo[mt][3],
                            a + (P8_ALO - P8_AHI));
                }
                #pragma unroll
                for (int nq = 0; nq < 4; nq++) {
                    const uint32_t b = bBase + bo + nq * (16 * 64) + bSw;
                    LDSM_X4(bhi[nq][0], bhi[nq][1], bhi[nq][2], bhi[nq][3], b);
                    LDSM_X4(blo[nq][0], blo[nq][1], blo[nq][2], blo[nq][3],
                            b + (P8_BLO - P8_BHI));
                }
                #pragma unroll
                for (int mt = 0; mt < 4; mt++)
                    #pragma unroll
                    for (int nq = 0; nq < 4; nq++)
                        #pragma unroll
                        for (int t = 0; t < 2; t++)
                            MMA16816(acc[mt][nq * 2 + t],
                                     ahi[mt][0], ahi[mt][1], ahi[mt][2], ahi[mt][3],
                                     bhi[nq][t * 2], bhi[nq][t * 2 + 1]);
                #pragma unroll
                for (int mt = 0; mt < 4; mt++)
                    #pragma unroll
                    for (int nq = 0; nq < 4; nq++)
                        #pragma unroll
                        for (int t = 0; t < 2; t++)
                            MMA16816(acc[mt][nq * 2 + t],
                                     ahi[mt][0], ahi[mt][1], ahi[mt][2], ahi[mt][3],
                                     blo[nq][t * 2], blo[nq][t * 2 + 1]);
                #pragma unroll
                for (int mt = 0; mt < 4; mt++)
                    #pragma unroll
                    for (int nq = 0; nq < 4; nq++)
                        #pragma unroll
                        for (int t = 0; t < 2; t++)
                            MMA16816(acc[mt][nq * 2 + t],
                                     alo[mt][0], alo[mt][1], alo[mt][2], alo[mt][3],
                                     bhi[nq][t * 2], bhi[nq][t * 2 + 1]);
            }

            const int nx = s + NS8 - 1;
            if (nx < nIter)
                issue(sbase + (uint32_t)((bufc + NS8 - 1) % NS8) * S8_BYTES,
                      Ah, Al, sA, Bh, Bl, sB, nx * 32, tid);
            CPCOMMIT();

            bufc = (bufc + 1 == NS8) ? 0 : bufc + 1;
        }
        __syncthreads();
    }
};

// ---------------------------------------------------------------------------
// Split fp32 tensors into bf16 hi/lo planes
// ---------------------------------------------------------------------------
__global__ __launch_bounds__(256) void split_inputs(
    const float* __restrict__ a0, const float* __restrict__ a1,
    const float* __restrict__ a2,
    __nv_bfloat16* __restrict__ h0, __nv_bfloat16* __restrict__ l0,
    __nv_bfloat16* __restrict__ h1, __nv_bfloat16* __restrict__ l1,
    __nv_bfloat16* __restrict__ h2, __nv_bfloat16* __restrict__ l2)
{
    const int z = blockIdx.y;
    const float* s = (z == 0) ? a0 : (z == 1) ? a1 : a2;
    __nv_bfloat16* H = (z == 0) ? h0 : (z == 1) ? h1 : h2;
    __nv_bfloat16* L = (z == 0) ? l0 : (z == 1) ? l1 : l2;
    const size_t i = ((size_t)blockIdx.x * 256 + threadIdx.x) * 4;
    float4 f = *(const float4*)(s + i);
    uint2 hi, lo;
    split4(f, hi, lo);
    *(uint2*)(H + i) = hi;
    *(uint2*)(L + i) = lo;
}

__global__ __launch_bounds__(256) void split_weights(
    const float* __restrict__ w0, const float* __restrict__ w1,
    const float* __restrict__ w2, const float* __restrict__ w3,
    __nv_bfloat16* __restrict__ wh, __nv_bfloat16* __restrict__ wl)
{
    const int z = blockIdx.y;
    const float* s = (z == 0) ? w0 : (z == 1) ? w1 : (z == 2) ? w2 : w3;
    const size_t base = (size_t)z * DD * DD;
    const size_t i = ((size_t)blockIdx.x * 256 + threadIdx.x) * 4;
    float4 f = *(const float4*)(s + i);
    uint2 hi, lo;
    split4(f, hi, lo);
    *(uint2*)(wh + base + i) = hi;
    *(uint2*)(wl + base + i) = lo;
}

// ---------------------------------------------------------------------------
// Batched Q/K/V projection (v8 core, 128 threads)
// ---------------------------------------------------------------------------
__global__ void proj_qkv(
    const __nv_bfloat16* __restrict__ qih, const __nv_bfloat16* __restrict__ qil,
    const __nv_bfloat16* __restrict__ kih, const __nv_bfloat16* __restrict__ kil,
    const __nv_bfloat16* __restrict__ vih, const __nv_bfloat16* __restrict__ vil,
    const __nv_bfloat16* __restrict__ wh, const __nv_bfloat16* __restrict__ wl,
    const float* __restrict__ bq, const float* __restrict__ bk,
    const float* __restrict__ bv,
    __nv_bfloat16* __restrict__ qh, __nv_bfloat16* __restrict__ ql,
    __nv_bfloat16* __restrict__ kh, __nv_bfloat16* __restrict__ kl,
    float* __restrict__ v)
{
    extern __shared__ char dsm[];
    const uint32_t sbase = smem_u32(dsm);
    const int tid  = threadIdx.x;
    const int lane = tid & 31;
    const int wid  = tid >> 5;
    const int wm   = wid >> 1;
    const int wn   = wid & 1;
    const int bn   = blockIdx.x;
    const int bm   = blockIdx.y;
    const int z    = blockIdx.z;

    const __nv_bfloat16* Ah = (z == 0) ? qih : (z == 1) ? kih : vih;
    const __nv_bfloat16* Al = (z == 0) ? qil : (z == 1) ? kil : vil;
    const float* bias = (z == 0) ? bq : (z == 1) ? bk : bv;
    const size_t wbase = (size_t)z * DD * DD;

    MmaB16v8 core;
    core.run(sbase,
             Ah + (size_t)(bm * 128) * DD, Al + (size_t)(bm * 128) * DD, DD,
             wh + wbase + (size_t)(bn * 128) * DD,
             wl + wbase + (size_t)(bn * 128) * DD, DD,
             DD / 32, tid);

    #pragma unroll
    for (int mt = 0; mt < 4; mt++) {
        const int row = bm * 128 + wm * 64 + mt * 16 + (lane >> 2);
        #pragma unroll
        for (int nt = 0; nt < 8; nt++) {
            const int col = bn * 128 + wn * 64 + nt * 8 + (lane & 3) * 2;
            const float b0 = bias[col], b1 = bias[col + 1];
            const float v0 = core.acc[mt][nt][0] + b0;
            const float v1 = core.acc[mt][nt][1] + b1;
            const float v2 = core.acc[mt][nt][2] + b0;
            const float v3 = core.acc[mt][nt][3] + b1;
            if (z == 2) {
                *(float2*)(v + (size_t)row * DD + col) = make_float2(v0, v1);
                *(float2*)(v + (size_t)(row + 8) * DD + col) = make_float2(v2, v3);
            } else {
                __nv_bfloat16* H = (z == 0) ? qh : kh;
                __nv_bfloat16* L = (z == 0) ? ql : kl;
                __nv_bfloat16 h0 = __float2bfloat16_rn(v0);
                __nv_bfloat16 h1 = __float2bfloat16_rn(v1);
                __nv_bfloat16 h2 = __float2bfloat16_rn(v2);
                __nv_bfloat16 h3 = __float2bfloat16_rn(v3);
                *(uint32_t*)(H + (size_t)row * DD + col) = pack_bf2(h0, h1);
                *(uint32_t*)(L + (size_t)row * DD + col) = pack_bf2(
                    __float2bfloat16_rn(v0 - __bfloat162float(h0)),
                    __float2bfloat16_rn(v1 - __bfloat162float(h1)));
                *(uint32_t*)(H + (size_t)(row + 8) * DD + col) = pack_bf2(h2, h3);
                *(uint32_t*)(L + (size_t)(row + 8) * DD + col) = pack_bf2(
                    __float2bfloat16_rn(v2 - __bfloat162float(h2)),
                    __float2bfloat16_rn(v3 - __bfloat162float(h3)));
            }
        }
    }
}

// ---------------------------------------------------------------------------
// Final GEMM (v8 core): out = x @ Wo^T + bo
// ---------------------------------------------------------------------------
__global__ void gemm_b16(
    const __nv_bfloat16* __restrict__ Ah, const __nv_bfloat16* __restrict__ Al,
    const __nv_bfloat16* __restrict__ Wh, const __nv_bfloat16* __restrict__ Wl,
    const float* __restrict__ bias, float* __restrict__ C)
{
    extern __shared__ char dsm[];
    const uint32_t sbase = smem_u32(dsm);
    const int tid  = threadIdx.x;
    const int lane = tid & 31;
    const int wid  = tid >> 5;
    const int wm   = wid >> 1;
    const int wn   = wid & 1;
    const int bn   = blockIdx.x;
    const int bm   = blockIdx.y;

    MmaB16v8 core;
    core.run(sbase,
             Ah + (size_t)(bm * 128) * DD, Al + (size_t)(bm * 128) * DD, DD,
             Wh + (size_t)(bn * 128) * DD, Wl + (size_t)(bn * 128) * DD, DD,
             DD / 32, tid);

    #pragma unroll
    for (int mt = 0; mt < 4; mt++) {
        const int row = bm * 128 + wm * 64 + mt * 16 + (lane >> 2);
        #pragma unroll
        for (int nt = 0; nt < 8; nt++) {
            const int col = bn * 128 + wn * 64 + nt * 8 + (lane & 3) * 2;
            const float b0 = bias[col], b1 = bias[col + 1];
            float2 o0, o1;
            o0.x = core.acc[mt][nt][0] + b0; o0.y = core.acc[mt][nt][1] + b1;
            o1.x = core.acc[mt][nt][2] + b0; o1.y = core.acc[mt][nt][3] + b1;
            *(float2*)(C + (size_t)row * DD + col) = o0;
            *(float2*)(C + (size_t)(row + 8) * DD + col) = o1;
        }
    }
}

// ---------------------------------------------------------------------------
// Scores+exp (v8 core, 128 threads): triangular grid; E planes + partials.
// ---------------------------------------------------------------------------
__global__ void scores_exp_kernel(
    const __nv_bfloat16* __restrict__ qh, const __nv_bfloat16* __restrict__ ql,
    const __nv_bfloat16* __restrict__ kh, const __nv_bfloat16* __restrict__ kl,
    __nv_bfloat16* __restrict__ eh, __nv_bfloat16* __restrict__ el,
    float* __restrict__ rpart)
{
    const int idx = blockIdx.x;            // 0..135 (lower-triangle tile id)
    int bm = (int)((sqrtf(8.f * idx + 1.f) - 1.f) * 0.5f);
    while ((bm + 1) * (bm + 2) / 2 <= idx) bm++;
    while (bm * (bm + 1) / 2 > idx) bm--;
    const int bn = idx - bm * (bm + 1) / 2;
    const int bh = blockIdx.y;
    const int tid = threadIdx.x;

    extern __shared__ char dsm[];
    __shared__ float rs[128][2];
    const uint32_t sbase = smem_u32(dsm);
    const int lane = tid & 31;
    const int wid  = tid >> 5;
    const int wm   = wid >> 1;
    const int wn   = wid & 1;
    const int b = bh / HH, h = bh % HH;

    const size_t aoff = (size_t)(b * SS + bm * 128) * DD + h * DK;
    const size_t boff = (size_t)(b * SS + bn * 128) * DD + h * DK;

    MmaB16v8 core;
    core.run(sbase, qh + aoff, ql + aoff, DD, kh + boff, kl + boff, DD,
             DK / 32, tid);

    __nv_bfloat16* peh = eh + (size_t)bh * SS * SS;
    __nv_bfloat16* pel = el + (size_t)bh * SS * SS;

    float rsum[4][2];
    #pragma unroll
    for (int mt = 0; mt < 4; mt++) { rsum[mt][0] = 0.f; rsum[mt][1] = 0.f; }

    #pragma unroll
    for (int mt = 0; mt < 4; mt++) {
        const int r0 = bm * 128 + wm * 64 + mt * 16 + (lane >> 2);
        const int r1 = r0 + 8;
        #pragma unroll
        for (int nt = 0; nt < 8; nt++) {
            const int col = bn * 128 + wn * 64 + nt * 8 + (lane & 3) * 2;
            float e0 = (col     <= r0) ? __expf(core.acc[mt][nt][0] * SCALE) : 0.f;
            float e1 = (col + 1 <= r0) ? __expf(core.acc[mt][nt][1] * SCALE) : 0.f;
            float e2 = (col     <= r1) ? __expf(core.acc[mt][nt][2] * SCALE) : 0.f;
            float e3 = (col + 1 <= r1) ? __expf(core.acc[mt][nt][3] * SCALE) : 0.f;
            rsum[mt][0] += e0 + e1;
            rsum[mt][1] += e2 + e3;
            __nv_bfloat16 h0 = __float2bfloat16_rn(e0);
            __nv_bfloat16 h1 = __float2bfloat16_rn(e1);
            __nv_bfloat16 h2 = __float2bfloat16_rn(e2);
            __nv_bfloat16 h3 = __float2bfloat16_rn(e3);
            *(uint32_t*)(peh + (size_t)r0 * SS + col) = pack_bf2(h0, h1);
            *(uint32_t*)(pel + (size_t)r0 * SS + col) = pack_bf2(
                __float2bfloat16_rn(e0 - __bfloat162float(h0)),
                __float2bfloat16_rn(e1 - __bfloat162float(h1)));
            *(uint32_t*)(peh + (size_t)r1 * SS + col) = pack_bf2(h2, h3);
            *(uint32_t*)(pel + (size_t)r1 * SS + col) = pack_bf2(
                __float2bfloat16_rn(e2 - __bfloat162float(h2)),
                __float2bfloat16_rn(e3 - __bfloat162float(h3)));
        }
    }

    #pragma unroll
    for (int mt = 0; mt < 4; mt++) {
        #pragma unroll
        for (int hf = 0; hf < 2; hf++) {
            float vv = rsum[mt][hf];
            vv += __shfl_xor_sync(0xffffffffu, vv, 1);
            vv += __shfl_xor_sync(0xffffffffu, vv, 2);
            if ((lane & 3) == 0) {
                const int lrow = wm * 64 + mt * 16 + hf * 8 + (lane >> 2);
                rs[lrow][wn] = vv;
            }
        }
    }
    __syncthreads();
    const float p = rs[tid][0] + rs[tid][1];
    rpart[((size_t)bh * SS + bm * 128 + tid) * 16 + bn] = p;
}

// ---------------------------------------------------------------------------
// ginv: 1/rowsum from partials
// ---------------------------------------------------------------------------
__global__ __launch_bounds__(256) void ginv_kernel(
    const float* __restrict__ rpart, float* __restrict__ ginv)
{
    const int i = blockIdx.x * 256 + threadIdx.x;   // bh*SS + s
    const int s = i & (SS - 1);
    const float* p = rpart + (size_t)i * 16;
    const int nb = (s >> 7) + 1;
    float sum = 0.f;
    for (int k = 0; k < nb; k++) sum += p[k];
    ginv[i] = 1.0f / sum;
}

// ---------------------------------------------------------------------------
// Zero the above-diagonal tail of attn (side stream)
// ---------------------------------------------------------------------------
__global__ __launch_bounds__(256) void zero_tail(float* __restrict__ attn)
{
    const int blk = blockIdx.x;           // bh*SS + s
    const int s   = blk & (SS - 1);
    const int limit = ((s >> 7) + 1) * 128;
    float* row = attn + (size_t)blk * SS;
    const float4 z = make_float4(0.f, 0.f, 0.f, 0.f);
    for (int j = limit + threadIdx.x * 4; j < SS; j += 1024)
        *(float4*)(row + j) = z;
}

// ---------------------------------------------------------------------------
// Finalize (prefix only): attn[0..limit) = (Eh+El)*inv. Tail pre-zeroed.
// ---------------------------------------------------------------------------
__global__ __launch_bounds__(256) void finalize_prefix(
    const __nv_bfloat16* __restrict__ eh, const __nv_bfloat16* __restrict__ el,
    const float* __restrict__ ginv, float* __restrict__ attn)
{
    const int blk = blockIdx.x;           // bh*SS + s
    const int s   = blk & (SS - 1);
    const float inv = ginv[blk];
    const __nv_bfloat16* reh = eh + (size_t)blk * SS;
    const __nv_bfloat16* rel = el + (size_t)blk * SS;
    float* row = attn + (size_t)blk * SS;
    const int limit = ((s >> 7) + 1) * 128;
    for (int j = threadIdx.x * 4; j < limit; j += 1024) {
        const __nv_bfloat162 h2 = *(const __nv_bfloat162*)(reh + j);
        const __nv_bfloat162 h3 = *(const __nv_bfloat162*)(reh + j + 2);
        const __nv_bfloat162 l2 = *(const __nv_bfloat162*)(rel + j);
        const __nv_bfloat162 l3 = *(const __nv_bfloat162*)(rel + j + 2);
        float4 o;
        o.x = (__bfloat162float(h2.x) + __bfloat162float(l2.x)) * inv;
        o.y = (__bfloat162float(h2.y) + __bfloat162float(l2.y)) * inv;
        o.z = (__bfloat162float(h3.x) + __bfloat162float(l3.x)) * inv;
        o.w = (__bfloat162float(h3.y) + __bfloat162float(l3.y)) * inv;
        *(float4*)(row + j) = o;
    }
}

// ---------------------------------------------------------------------------
// Transpose V per head into bf16 hi/lo planes: vt[bh][d][s]
// ---------------------------------------------------------------------------
__global__ __launch_bounds__(256) void transpose_v(
    const float* __restrict__ v,
    __nv_bfloat16* __restrict__ vth, __nv_bfloat16* __restrict__ vtl)
{
    __shared__ float t[32][33];
    const int bh = blockIdx.z, b = bh / HH, h = bh % HH;
    const int s0 = blockIdx.x * 32, d0 = blockIdx.y * 32;
    const int tx = threadIdx.x & 31, ty = threadIdx.x >> 5;
    #pragma unroll
    for (int i = 0; i < 4; i++)
        t[ty + i * 8][tx] =
            v[(size_t)(b * SS + s0 + ty + i * 8) * DD + h * DK + d0 + tx];
    __syncthreads();
    #pragma unroll
    for (int i = 0; i < 4; i++) {
        const float f = t[tx][ty + i * 8];
        const __nv_bfloat16 hh = __float2bfloat16_rn(f);
        const __nv_bfloat16 ll = __float2bfloat16_rn(f - __bfloat162float(hh));
        const size_t idx = (size_t)bh * DK * SS + (size_t)(d0 + ty + i * 8) * SS
                         + s0 + tx;
        vth[idx] = hh;
        vtl[idx] = ll;
    }
}

// ---------------------------------------------------------------------------
// AV (v8 core, 128 threads): x = (E @ V) * inv; heavy-first 1D grid.
// ---------------------------------------------------------------------------
__global__ void av_mma_kernel(
    const __nv_bfloat16* __restrict__ eh, const __nv_bfloat16* __restrict__ el,
    const __nv_bfloat16* __restrict__ vth, const __nv_bfloat16* __restrict__ vtl,
    const float* __restrict__ ginv,
    __nv_bfloat16* __restrict__ xh, __nv_bfloat16* __restrict__ xl)
{
    const int t = blockIdx.x;              // 0..511, heavy bm first
    const int bm = 15 - (t >> 5);
    const int bh = t & 31;
    extern __shared__ char dsm[];
    const uint32_t sbase = smem_u32(dsm);
    const int b = bh / HH, h = bh % HH;
    const int tid  = threadIdx.x;
    const int lane = tid & 31;
    const int wid  = tid >> 5;
    const int wm   = wid >> 1;
    const int wn   = wid & 1;

    const size_t aoff = (size_t)bh * SS * SS + (size_t)(bm * 128) * SS;
    const size_t boff = (size_t)bh * DK * SS;

    MmaB16v8 core;
    core.run(sbase, eh + aoff, el + aoff, SS, vth + boff, vtl + boff, SS,
             (bm + 1) * 4, tid);

    #pragma unroll
    for (int mt = 0; mt < 4; mt++) {
        const int row = bm * 128 + wm * 64 + mt * 16 + (lane >> 2);
        const float inv0 = ginv[(size_t)bh * SS + row];
        const float inv1 = ginv[(size_t)bh * SS + row + 8];
        #pragma unroll
        for (int nt = 0; nt < 8; nt++) {
            const int col = wn * 64 + nt * 8 + (lane & 3) * 2;
            const float v0 = core.acc[mt][nt][0] * inv0;
            const float v1 = core.acc[mt][nt][1] * inv0;
            const float v2 = core.acc[mt][nt][2] * inv1;
            const float v3 = core.acc[mt][nt][3] * inv1;
            __nv_bfloat16 h0 = __float2bfloat16_rn(v0);
            __nv_bfloat16 h1 = __float2bfloat16_rn(v1);
            __nv_bfloat16 h2 = __float2bfloat16_rn(v2);
            __nv_bfloat16 h3 = __float2bfloat16_rn(v3);
            const size_t o0 = (size_t)(b * SS + row) * DD + h * DK + col;
            const size_t o1 = (size_t)(b * SS + row + 8) * DD + h * DK + col;
            *(uint32_t*)(xh + o0) = pack_bf2(h0, h1);
            *(uint32_t*)(xl + o0) = pack_bf2(
                __float2bfloat16_rn(v0 - __bfloat162float(h0)),
                __float2bfloat16_rn(v1 - __bfloat162float(h1)));
            *(uint32_t*)(xh + o1) = pack_bf2(h2, h3);
            *(uint32_t*)(xl + o1) = pack_bf2(
                __float2bfloat16_rn(v2 - __bfloat162float(h2)),
                __float2bfloat16_rn(v3 - __bfloat162float(h3)));
        }
    }
}

// ---------------------------------------------------------------------------
extern "C" void kernel_launch(void* const* d_in, const int* in_sizes, int n_in,
                              void* d_out, int out_size)
{
    const float* query = (const float*)d_in[0];
    const float* key   = (const float*)d_in[1];
    const float* value = (const float*)d_in[2];
    const float* Wq = (const float*)d_in[3];
    const float* bq = (const float*)d_in[4];
    const float* Wk = (const float*)d_in[5];
    const float* bk = (const float*)d_in[6];
    const float* Wv = (const float*)d_in[7];
    const float* bv = (const float*)d_in[8];
    const float* Wo = (const float*)d_in[9];
    const float* bo = (const float*)d_in[10];

    float* out  = (float*)d_out;                       // [4096, 2048]
    float* attn = out + (size_t)MTOK * DD;             // [32, 2048, 2048]

    float *v, *rpart, *ginv;
    __nv_bfloat16 *qih, *qil, *kih, *kil, *vih, *vil, *wh, *wl;
    __nv_bfloat16 *qh, *ql, *kh, *kl, *xh, *xl, *vth, *vtl, *eh, *el;
    cudaGetSymbolAddress((void**)&v, g_v);
    cudaGetSymbolAddress((void**)&rpart, g_rpart);
    cudaGetSymbolAddress((void**)&ginv, g_inv);
    cudaGetSymbolAddress((void**)&qih, g_qih);
    cudaGetSymbolAddress((void**)&qil, g_qil);
    cudaGetSymbolAddress((void**)&kih, g_kih);
    cudaGetSymbolAddress((void**)&kil, g_kil);
    cudaGetSymbolAddress((void**)&vih, g_vih);
    cudaGetSymbolAddress((void**)&vil, g_vil);
    cudaGetSymbolAddress((void**)&wh, g_wh);
    cudaGetSymbolAddress((void**)&wl, g_wl);
    cudaGetSymbolAddress((void**)&qh, g_qh);
    cudaGetSymbolAddress((void**)&ql, g_ql);
    cudaGetSymbolAddress((void**)&kh, g_kh);
    cudaGetSymbolAddress((void**)&kl, g_kl);
    cudaGetSymbolAddress((void**)&xh, g_xh);
    cudaGetSymbolAddress((void**)&xl, g_xl);
    cudaGetSymbolAddress((void**)&vth, g_vth);
    cudaGetSymbolAddress((void**)&vtl, g_vtl);
    cudaGetSymbolAddress((void**)&eh, g_eh);
    cudaGetSymbolAddress((void**)&el, g_el);

    static cudaStream_t s1 = nullptr;
    static cudaEvent_t evA = nullptr, evB = nullptr, evF = nullptr;
    static cudaEvent_t evP = nullptr, evT = nullptr;
    if (s1 == nullptr) {
        cudaStreamCreateWithFlags(&s1, cudaStreamNonBlocking);
        cudaEventCreateWithFlags(&evA, cudaEventDisableTiming);
        cudaEventCreateWithFlags(&evB, cudaEventDisableTiming);
        cudaEventCreateWithFlags(&evF, cudaEventDisableTiming);
        cudaEventCreateWithFlags(&evP, cudaEventDisableTiming);
        cudaEventCreateWithFlags(&evT, cudaEventDisableTiming);
        cudaFuncSetAttribute(proj_qkv,
            cudaFuncAttributeMaxDynamicSharedMemorySize, DSMEM_V8);
        cudaFuncSetAttribute(gemm_b16,
            cudaFuncAttributeMaxDynamicSharedMemorySize, DSMEM_V8);
        cudaFuncSetAttribute(scores_exp_kernel,
            cudaFuncAttributeMaxDynamicSharedMemorySize, DSMEM_V8);
        cudaFuncSetAttribute(av_mma_kernel,
            cudaFuncAttributeMaxDynamicSharedMemorySize, DSMEM_V8);
    }

    // Fork side stream: zero the above-diagonal attn tail (no dependencies)
    cudaEventRecord(evA, 0);
    cudaStreamWaitEvent(s1, evA, 0);
    zero_tail<<<BB * HH * SS, 256, 0, s1>>>(attn);

    // Main stream: splits -> proj
    dim3 gsi((MTOK * DD) / (256 * 4), 3);
    split_inputs<<<gsi, 256>>>(query, key, value,
                               qih, qil, kih, kil, vih, vil);
    dim3 gsw((DD * DD) / (256 * 4), 4);
    split_weights<<<gsw, 256>>>(Wq, Wk, Wv, Wo, wh, wl);

    dim3 gproj(DD / 128, MTOK / 128, 3);                // (16, 32, 3)
    proj_qkv<<<gproj, 128, DSMEM_V8>>>(
        qih, qil, kih, kil, vih, vil, wh, wl, bq, bk, bv,
        qh, ql, kh, kl, v);

    // Side stream: V transpose (scores doesn't need it; AV does)
    cudaEventRecord(evP, 0);
    cudaStreamWaitEvent(s1, evP, 0);
    dim3 gtr(SS / 32, DK / 32, BB * HH);
    transpose_v<<<gtr, 256, 0, s1>>>(v, vth, vtl);
    cudaEventRecord(evT, s1);

    // Main stream: scores -> ginv
    dim3 gsc(136, BB * HH);
    scores_exp_kernel<<<gsc, 128, DSMEM_V8>>>(qh, ql, kh, kl, eh, el, rpart);

    ginv_kernel<<<(BB * HH * SS) / 256, 256>>>(rpart, ginv);

    // Side stream: finalize attn prefix (overlaps AV + output projection)
    cudaEventRecord(evB, 0);
    cudaStreamWaitEvent(s1, evB, 0);
    finalize_prefix<<<BB * HH * SS, 256, 0, s1>>>(eh, el, ginv, attn);
    cudaEventRecord(evF, s1);

    // Main stream: AV (needs vt from side stream), output projection
    cudaStreamWaitEvent(0, evT, 0);
    av_mma_kernel<<<512, 128, DSMEM_V8>>>(eh, el, vth, vtl, ginv, xh, xl);

    dim3 gout(DD / 128, MTOK / 128);                    // (16, 32)
    gemm_b16<<<gout, 128, DSMEM_V8>>>(
        xh, xl, wh + (size_t)3 * DD * DD, wl + (size_t)3 * DD * DD, bo, out);

    // Join side stream into the graph
    cudaStreamWaitEvent(0, evF, 0);
}

// round 16
// speedup vs baseline: 1.3290x; 1.3290x over previous
#include <cuda_runtime.h>
#include <cuda_bf16.h>
#include <cstdint>
#include <math.h>

// ---------------------------------------------------------------------------
// Problem constants
// ---------------------------------------------------------------------------
#define BB   2
#define SS   2048
#define DD   2048
#define HH   16
#define DK   128
#define MTOK (BB * SS)          // 4096 tokens
#define SCALE 0.08838834764831845f  // 1/sqrt(128)

// Scratch (device globals; no cudaMalloc allowed)
static __device__ float g_v [(size_t)MTOK * DD];
static __device__ float g_rpart[(size_t)BB * HH * SS * 16];
static __device__ float g_inv[(size_t)BB * HH * SS];
// bf16 hi/lo planes
static __device__ __nv_bfloat16 g_qih[(size_t)MTOK * DD], g_qil[(size_t)MTOK * DD];
static __device__ __nv_bfloat16 g_kih[(size_t)MTOK * DD], g_kil[(size_t)MTOK * DD];
static __device__ __nv_bfloat16 g_vih[(size_t)MTOK * DD], g_vil[(size_t)MTOK * DD];
static __device__ __nv_bfloat16 g_wh[(size_t)4 * DD * DD], g_wl[(size_t)4 * DD * DD];
static __device__ __nv_bfloat16 g_qh[(size_t)MTOK * DD], g_ql[(size_t)MTOK * DD];
static __device__ __nv_bfloat16 g_kh[(size_t)MTOK * DD], g_kl[(size_t)MTOK * DD];
static __device__ __nv_bfloat16 g_xh[(size_t)MTOK * DD], g_xl[(size_t)MTOK * DD];
static __device__ __nv_bfloat16 g_vth[(size_t)BB * HH * DK * SS];
static __device__ __nv_bfloat16 g_vtl[(size_t)BB * HH * DK * SS];
// Unnormalized-E planes
static __device__ __nv_bfloat16 g_eh[(size_t)BB * HH * SS * SS];
static __device__ __nv_bfloat16 g_el[(size_t)BB * HH * SS * SS];

// ---------------------------------------------------------------------------
// PTX helpers
// ---------------------------------------------------------------------------
#define LDSM_X4(r0, r1, r2, r3, addr) \
    asm volatile("ldmatrix.sync.aligned.m8n8.x4.shared.b16 {%0,%1,%2,%3}, [%4];" \
        : "=r"(r0), "=r"(r1), "=r"(r2), "=r"(r3) : "r"(addr))

#define MMA16816(c, a0, a1, a2, a3, b0, b1) \
    asm volatile("mma.sync.aligned.m16n8k16.row.col.f32.bf16.bf16.f32 " \
        "{%0,%1,%2,%3}, {%4,%5,%6,%7}, {%8,%9}, {%0,%1,%2,%3};" \
        : "+f"((c)[0]), "+f"((c)[1]), "+f"((c)[2]), "+f"((c)[3]) \
        : "r"(a0), "r"(a1), "r"(a2), "r"(a3), "r"(b0), "r"(b1))

#define CP16(dst, src) \
    asm volatile("cp.async.cg.shared.global [%0], [%1], 16;" \
        :: "r"(dst), "l"(src))
#define CPCOMMIT() asm volatile("cp.async.commit_group;" ::: "memory")
#define CPWAIT2()  asm volatile("cp.async.wait_group 2;" ::: "memory")

__device__ __forceinline__ uint32_t smem_u32(const void* p) {
    uint32_t a;
    asm("{ .reg .u64 t; cvta.to.shared.u64 t, %1; cvt.u32.u64 %0, t; }"
        : "=r"(a) : "l"(p));
    return a;
}

__device__ __forceinline__ uint32_t pack_bf2(__nv_bfloat16 a, __nv_bfloat16 b) {
    return (uint32_t)__bfloat16_as_ushort(a) |
           ((uint32_t)__bfloat16_as_ushort(b) << 16);
}

__device__ __forceinline__ void split4(const float4 f, uint2& hi, uint2& lo) {
    __nv_bfloat16 h0 = __float2bfloat16_rn(f.x);
    __nv_bfloat16 h1 = __float2bfloat16_rn(f.y);
    __nv_bfloat16 h2 = __float2bfloat16_rn(f.z);
    __nv_bfloat16 h3 = __float2bfloat16_rn(f.w);
    __nv_bfloat16 l0 = __float2bfloat16_rn(f.x - __bfloat162float(h0));
    __nv_bfloat16 l1 = __float2bfloat16_rn(f.y - __bfloat162float(h1));
    __nv_bfloat16 l2 = __float2bfloat16_rn(f.z - __bfloat162float(h2));
    __nv_bfloat16 l3 = __float2bfloat16_rn(f.w - __bfloat162float(h3));
    hi.x = pack_bf2(h0, h1); hi.y = pack_bf2(h2, h3);
    lo.x = pack_bf2(l0, l1); lo.y = pack_bf2(l2, l3);
}

#define RS2 48
#define NS 4
#define ST_AHI 0
#define ST_ALO 6144
#define ST_BHI 12288
#define ST_BLO 18432
#define ST_BYTES 24576
#define DSMEM_V6 (NS * ST_BYTES)   // 98304

// ---------------------------------------------------------------------------
// MmaB16v6: 128x128 tile, 128 threads (4 warps, 64x64 warp tile),
// K-chunk 16, 4-stage cp.async pipeline, 2 CTAs/SM, natural regs (~198).
// Proven R13 config: MMA:LDSM = 6:1, term-ordered MMAs.
// ---------------------------------------------------------------------------
struct MmaB16v6 {
    float acc[4][8][4];

    __device__ __forceinline__ static void issue(
        uint32_t sb,
        const __nv_bfloat16* Ah, const __nv_bfloat16* Al, size_t sA,
        const __nv_bfloat16* Bh, const __nv_bfloat16* Bl, size_t sB,
        int k0, int tid)
    {
        const int r0   = tid >> 1;
        const int half = tid & 1;
        #pragma unroll
        for (int p = 0; p < 2; p++) {
            const int r = r0 + p * 64;
            const uint32_t so = (uint32_t)r * RS2 + half * 16;
            const size_t oA = (size_t)r * sA + k0 + half * 8;
            const size_t oB = (size_t)r * sB + k0 + half * 8;
            CP16(sb + ST_AHI + so, Ah + oA);
            CP16(sb + ST_ALO + so, Al + oA);
            CP16(sb + ST_BHI + so, Bh + oB);
            CP16(sb + ST_BLO + so, Bl + oB);
        }
    }

    __device__ __forceinline__ void run(
        uint32_t sbase,
        const __nv_bfloat16* Ah, const __nv_bfloat16* Al, size_t sA,
        const __nv_bfloat16* Bh, const __nv_bfloat16* Bl, size_t sB,
        const int nIter, const int tid)
    {
        const int lane = tid & 31;
        const int wid  = tid >> 5;
        const int wm   = wid >> 1;
        const int wn   = wid & 1;

        #pragma unroll
        for (int i = 0; i < 4; i++)
            #pragma unroll
            for (int j = 0; j < 8; j++)
                #pragma unroll
                for (int c = 0; c < 4; c++) acc[i][j][c] = 0.0f;

        const uint32_t aAddr = sbase + ST_AHI
            + (uint32_t)(wm * 64 + (lane & 15)) * RS2 + (lane >> 4) * 16;
        const uint32_t bAddr = sbase + ST_BHI
            + (uint32_t)(wn * 64 + (lane & 7) + ((lane >> 4) & 1) * 8) * RS2
            + ((lane >> 3) & 1) * 16;

        #pragma unroll
        for (int p = 0; p < NS - 1; p++) {
            if (p < nIter)
                issue(sbase + p * ST_BYTES, Ah, Al, sA, Bh, Bl, sB, p * 16, tid);
            CPCOMMIT();
        }

        for (int s = 0; s < nIter; s++) {
            CPWAIT2();
            __syncthreads();

            const uint32_t bo = (uint32_t)(s & (NS - 1)) * ST_BYTES;
            uint32_t ahi[4][4], alo[4][4];
            uint32_t bhi[4][4], blo[4][4];
            #pragma unroll
            for (int mt = 0; mt < 4; mt++) {
                const uint32_t a = aAddr + bo + mt * (16 * RS2);
                LDSM_X4(ahi[mt][0], ahi[mt][1], ahi[mt][2], ahi[mt][3], a);
                LDSM_X4(alo[mt][0], alo[mt][1], alo[mt][2], alo[mt][3],
                        a + (ST_ALO - ST_AHI));
            }
            #pragma unroll
            for (int nq = 0; nq < 4; nq++) {
                const uint32_t b = bAddr + bo + nq * (16 * RS2);
                LDSM_X4(bhi[nq][0], bhi[nq][1], bhi[nq][2], bhi[nq][3], b);
                LDSM_X4(blo[nq][0], blo[nq][1], blo[nq][2], blo[nq][3],
                        b + (ST_BLO - ST_BHI));
            }
            #pragma unroll
            for (int mt = 0; mt < 4; mt++)
                #pragma unroll
                for (int nq = 0; nq < 4; nq++)
                    #pragma unroll
                    for (int t = 0; t < 2; t++)
                        MMA16816(acc[mt][nq * 2 + t],
                                 ahi[mt][0], ahi[mt][1], ahi[mt][2], ahi[mt][3],
                                 bhi[nq][t * 2], bhi[nq][t * 2 + 1]);
            #pragma unroll
            for (int mt = 0; mt < 4; mt++)
                #pragma unroll
                for (int nq = 0; nq < 4; nq++)
                    #pragma unroll
                    for (int t = 0; t < 2; t++)
                        MMA16816(acc[mt][nq * 2 + t],
                                 ahi[mt][0], ahi[mt][1], ahi[mt][2], ahi[mt][3],
                                 blo[nq][t * 2], blo[nq][t * 2 + 1]);
            #pragma unroll
            for (int mt = 0; mt < 4; mt++)
                #pragma unroll
                for (int nq = 0; nq < 4; nq++)
                    #pragma unroll
                    for (int t = 0; t < 2; t++)
                        MMA16816(acc[mt][nq * 2 + t],
                                 alo[mt][0], alo[mt][1], alo[mt][2], alo[mt][3],
                                 bhi[nq][t * 2], bhi[nq][t * 2 + 1]);

            const int nx = s + NS - 1;
            if (nx < nIter)
                issue(sbase + (uint32_t)(nx & (NS - 1)) * ST_BYTES,
                      Ah, Al, sA, Bh, Bl, sB, nx * 16, tid);
            CPCOMMIT();
        }
        __syncthreads();
    }
};

// ---------------------------------------------------------------------------
// Split fp32 tensors into bf16 hi/lo planes
// ---------------------------------------------------------------------------
__global__ __launch_bounds__(256) void split_inputs(
    const float* __restrict__ a0, const float* __restrict__ a1,
    const float* __restrict__ a2,
    __nv_bfloat16* __restrict__ h0, __nv_bfloat16* __restrict__ l0,
    __nv_bfloat16* __restrict__ h1, __nv_bfloat16* __restrict__ l1,
    __nv_bfloat16* __restrict__ h2, __nv_bfloat16* __restrict__ l2)
{
    const int z = blockIdx.y;
    const float* s = (z == 0) ? a0 : (z == 1) ? a1 : a2;
    __nv_bfloat16* H = (z == 0) ? h0 : (z == 1) ? h1 : h2;
    __nv_bfloat16* L = (z == 0) ? l0 : (z == 1) ? l1 : l2;
    const size_t i = ((size_t)blockIdx.x * 256 + threadIdx.x) * 4;
    float4 f = *(const float4*)(s + i);
    uint2 hi, lo;
    split4(f, hi, lo);
    *(uint2*)(H + i) = hi;
    *(uint2*)(L + i) = lo;
}

__global__ __launch_bounds__(256) void split_weights(
    const float* __restrict__ w0, const float* __restrict__ w1,
    const float* __restrict__ w2, const float* __restrict__ w3,
    __nv_bfloat16* __restrict__ wh, __nv_bfloat16* __restrict__ wl)
{
    const int z = blockIdx.y;
    const float* s = (z == 0) ? w0 : (z == 1) ? w1 : (z == 2) ? w2 : w3;
    const size_t base = (size_t)z * DD * DD;
    const size_t i = ((size_t)blockIdx.x * 256 + threadIdx.x) * 4;
    float4 f = *(const float4*)(s + i);
    uint2 hi, lo;
    split4(f, hi, lo);
    *(uint2*)(wh + base + i) = hi;
    *(uint2*)(wl + base + i) = lo;
}

// ---------------------------------------------------------------------------
// Batched Q/K/V projection (v6 core, 128 threads)
// ---------------------------------------------------------------------------
__global__ void proj_qkv(
    const __nv_bfloat16* __restrict__ qih, const __nv_bfloat16* __restrict__ qil,
    const __nv_bfloat16* __restrict__ kih, const __nv_bfloat16* __restrict__ kil,
    const __nv_bfloat16* __restrict__ vih, const __nv_bfloat16* __restrict__ vil,
    const __nv_bfloat16* __restrict__ wh, const __nv_bfloat16* __restrict__ wl,
    const float* __restrict__ bq, const float* __restrict__ bk,
    const float* __restrict__ bv,
    __nv_bfloat16* __restrict__ qh, __nv_bfloat16* __restrict__ ql,
    __nv_bfloat16* __restrict__ kh, __nv_bfloat16* __restrict__ kl,
    float* __restrict__ v)
{
    extern __shared__ char dsm[];
    const uint32_t sbase = smem_u32(dsm);
    const int tid  = threadIdx.x;
    const int lane = tid & 31;
    const int wid  = tid >> 5;
    const int wm   = wid >> 1;
    const int wn   = wid & 1;
    const int bn   = blockIdx.x;
    const int bm   = blockIdx.y;
    const int z    = blockIdx.z;

    const __nv_bfloat16* Ah = (z == 0) ? qih : (z == 1) ? kih : vih;
    const __nv_bfloat16* Al = (z == 0) ? qil : (z == 1) ? kil : vil;
    const float* bias = (z == 0) ? bq : (z == 1) ? bk : bv;
    const size_t wbase = (size_t)z * DD * DD;

    MmaB16v6 core;
    core.run(sbase,
             Ah + (size_t)(bm * 128) * DD, Al + (size_t)(bm * 128) * DD, DD,
             wh + wbase + (size_t)(bn * 128) * DD,
             wl + wbase + (size_t)(bn * 128) * DD, DD,
             DD / 16, tid);

    #pragma unroll
    for (int mt = 0; mt < 4; mt++) {
        const int row = bm * 128 + wm * 64 + mt * 16 + (lane >> 2);
        #pragma unroll
        for (int nt = 0; nt < 8; nt++) {
            const int col = bn * 128 + wn * 64 + nt * 8 + (lane & 3) * 2;
            const float b0 = bias[col], b1 = bias[col + 1];
            const float v0 = core.acc[mt][nt][0] + b0;
            const float v1 = core.acc[mt][nt][1] + b1;
            const float v2 = core.acc[mt][nt][2] + b0;
            const float v3 = core.acc[mt][nt][3] + b1;
            if (z == 2) {
                *(float2*)(v + (size_t)row * DD + col) = make_float2(v0, v1);
                *(float2*)(v + (size_t)(row + 8) * DD + col) = make_float2(v2, v3);
            } else {
                __nv_bfloat16* H = (z == 0) ? qh : kh;
                __nv_bfloat16* L = (z == 0) ? ql : kl;
                __nv_bfloat16 h0 = __float2bfloat16_rn(v0);
                __nv_bfloat16 h1 = __float2bfloat16_rn(v1);
                __nv_bfloat16 h2 = __float2bfloat16_rn(v2);
                __nv_bfloat16 h3 = __float2bfloat16_rn(v3);
                *(uint32_t*)(H + (size_t)row * DD + col) = pack_bf2(h0, h1);
                *(uint32_t*)(L + (size_t)row * DD + col) = pack_bf2(
                    __float2bfloat16_rn(v0 - __bfloat162float(h0)),
                    __float2bfloat16_rn(v1 - __bfloat162float(h1)));
                *(uint32_t*)(H + (size_t)(row + 8) * DD + col) = pack_bf2(h2, h3);
                *(uint32_t*)(L + (size_t)(row + 8) * DD + col) = pack_bf2(
                    __float2bfloat16_rn(v2 - __bfloat162float(h2)),
                    __float2bfloat16_rn(v3 - __bfloat162float(h3)));
            }
        }
    }
}

// ---------------------------------------------------------------------------
// Final GEMM (v6 core): out = x @ Wo^T + bo
// ---------------------------------------------------------------------------
__global__ void gemm_b16(
    const __nv_bfloat16* __restrict__ Ah, const __nv_bfloat16* __restrict__ Al,
    const __nv_bfloat16* __restrict__ Wh, const __nv_bfloat16* __restrict__ Wl,
    const float* __restrict__ bias, float* __restrict__ C)
{
    extern __shared__ char dsm[];
    const uint32_t sbase = smem_u32(dsm);
    const int tid  = threadIdx.x;
    const int lane = tid & 31;
    const int wid  = tid >> 5;
    const int wm   = wid >> 1;
    const int wn   = wid & 1;
    const int bn   = blockIdx.x;
    const int bm   = blockIdx.y;

    MmaB16v6 core;
    core.run(sbase,
             Ah + (size_t)(bm * 128) * DD, Al + (size_t)(bm * 128) * DD, DD,
             Wh + (size_t)(bn * 128) * DD, Wl + (size_t)(bn * 128) * DD, DD,
             DD / 16, tid);

    #pragma unroll
    for (int mt = 0; mt < 4; mt++) {
        const int row = bm * 128 + wm * 64 + mt * 16 + (lane >> 2);
        #pragma unroll
        for (int nt = 0; nt < 8; nt++) {
            const int col = bn * 128 + wn * 64 + nt * 8 + (lane & 3) * 2;
            const float b0 = bias[col], b1 = bias[col + 1];
            float2 o0, o1;
            o0.x = core.acc[mt][nt][0] + b0; o0.y = core.acc[mt][nt][1] + b1;
            o1.x = core.acc[mt][nt][2] + b0; o1.y = core.acc[mt][nt][3] + b1;
            *(float2*)(C + (size_t)row * DD + col) = o0;
            *(float2*)(C + (size_t)(row + 8) * DD + col) = o1;
        }
    }
}

// ---------------------------------------------------------------------------
// Scores+exp (v6 core, 128 threads): triangular grid; E planes + partials.
// ---------------------------------------------------------------------------
__global__ void scores_exp_kernel(
    const __nv_bfloat16* __restrict__ qh, const __nv_bfloat16* __restrict__ ql,
    const __nv_bfloat16* __restrict__ kh, const __nv_bfloat16* __restrict__ kl,
    __nv_bfloat16* __restrict__ eh, __nv_bfloat16* __restrict__ el,
    float* __restrict__ rpart)
{
    const int idx = blockIdx.x;            // 0..135 (lower-triangle tile id)
    int bm = (int)((sqrtf(8.f * idx + 1.f) - 1.f) * 0.5f);
    while ((bm + 1) * (bm + 2) / 2 <= idx) bm++;
    while (bm * (bm + 1) / 2 > idx) bm--;
    const int bn = idx - bm * (bm + 1) / 2;
    const int bh = blockIdx.y;
    const int tid = threadIdx.x;

    extern __shared__ char dsm[];
    __shared__ float rs[128][2];
    const uint32_t sbase = smem_u32(dsm);
    const int lane = tid & 31;
    const int wid  = tid >> 5;
    const int wm   = wid >> 1;
    const int wn   = wid & 1;
    const int b = bh / HH, h = bh % HH;

    const size_t aoff = (size_t)(b * SS + bm * 128) * DD + h * DK;
    const size_t boff = (size_t)(b * SS + bn * 128) * DD + h * DK;

    MmaB16v6 core;
    core.run(sbase, qh + aoff, ql + aoff, DD, kh + boff, kl + boff, DD,
             DK / 16, tid);

    __nv_bfloat16* peh = eh + (size_t)bh * SS * SS;
    __nv_bfloat16* pel = el + (size_t)bh * SS * SS;

    float rsum[4][2];
    #pragma unroll
    for (int mt = 0; mt < 4; mt++) { rsum[mt][0] = 0.f; rsum[mt][1] = 0.f; }

    #pragma unroll
    for (int mt = 0; mt < 4; mt++) {
        const int r0 = bm * 128 + wm * 64 + mt * 16 + (lane >> 2);
        const int r1 = r0 + 8;
        #pragma unroll
        for (int nt = 0; nt < 8; nt++) {
            const int col = bn * 128 + wn * 64 + nt * 8 + (lane & 3) * 2;
            float e0 = (col     <= r0) ? __expf(core.acc[mt][nt][0] * SCALE) : 0.f;
            float e1 = (col + 1 <= r0) ? __expf(core.acc[mt][nt][1] * SCALE) : 0.f;
            float e2 = (col     <= r1) ? __expf(core.acc[mt][nt][2] * SCALE) : 0.f;
            float e3 = (col + 1 <= r1) ? __expf(core.acc[mt][nt][3] * SCALE) : 0.f;
            rsum[mt][0] += e0 + e1;
            rsum[mt][1] += e2 + e3;
            __nv_bfloat16 h0 = __float2bfloat16_rn(e0);
            __nv_bfloat16 h1 = __float2bfloat16_rn(e1);
            __nv_bfloat16 h2 = __float2bfloat16_rn(e2);
            __nv_bfloat16 h3 = __float2bfloat16_rn(e3);
            *(uint32_t*)(peh + (size_t)r0 * SS + col) = pack_bf2(h0, h1);
            *(uint32_t*)(pel + (size_t)r0 * SS + col) = pack_bf2(
                __float2bfloat16_rn(e0 - __bfloat162float(h0)),
                __float2bfloat16_rn(e1 - __bfloat162float(h1)));
            *(uint32_t*)(peh + (size_t)r1 * SS + col) = pack_bf2(h2, h3);
            *(uint32_t*)(pel + (size_t)r1 * SS + col) = pack_bf2(
                __float2bfloat16_rn(e2 - __bfloat162float(h2)),
                __float2bfloat16_rn(e3 - __bfloat162float(h3)));
        }
    }

    #pragma unroll
    for (int mt = 0; mt < 4; mt++) {
        #pragma unroll
        for (int hf = 0; hf < 2; hf++) {
            float vv = rsum[mt][hf];
            vv += __shfl_xor_sync(0xffffffffu, vv, 1);
            vv += __shfl_xor_sync(0xffffffffu, vv, 2);
            if ((lane & 3) == 0) {
                const int lrow = wm * 64 + mt * 16 + hf * 8 + (lane >> 2);
                rs[lrow][wn] = vv;
            }
        }
    }
    __syncthreads();
    const float p = rs[tid][0] + rs[tid][1];
    rpart[((size_t)bh * SS + bm * 128 + tid) * 16 + bn] = p;
}

// ---------------------------------------------------------------------------
// ginv: 1/rowsum from partials
// ---------------------------------------------------------------------------
__global__ __launch_bounds__(256) void ginv_kernel(
    const float* __restrict__ rpart, float* __restrict__ ginv)
{
    const int i = blockIdx.x * 256 + threadIdx.x;   // bh*SS + s
    const int s = i & (SS - 1);
    const float* p = rpart + (size_t)i * 16;
    const int nb = (s >> 7) + 1;
    float sum = 0.f;
    for (int k = 0; k < nb; k++) sum += p[k];
    ginv[i] = 1.0f / sum;
}

// ---------------------------------------------------------------------------
// Zero the above-diagonal tail of attn (side stream)
// ---------------------------------------------------------------------------
__global__ __launch_bounds__(256) void zero_tail(float* __restrict__ attn)
{
    const int blk = blockIdx.x;           // bh*SS + s
    const int s   = blk & (SS - 1);
    const int limit = ((s >> 7) + 1) * 128;
    float* row = attn + (size_t)blk * SS;
    const float4 z = make_float4(0.f, 0.f, 0.f, 0.f);
    for (int j = limit + threadIdx.x * 4; j < SS; j += 1024)
        *(float4*)(row + j) = z;
}

// ---------------------------------------------------------------------------
// Finalize (prefix only): attn[0..limit) = (Eh+El)*inv. Tail pre-zeroed.
// ---------------------------------------------------------------------------
__global__ __launch_bounds__(256) void finalize_prefix(
    const __nv_bfloat16* __restrict__ eh, const __nv_bfloat16* __restrict__ el,
    const float* __restrict__ ginv, float* __restrict__ attn)
{
    const int blk = blockIdx.x;           // bh*SS + s
    const int s   = blk & (SS - 1);
    const float inv = ginv[blk];
    const __nv_bfloat16* reh = eh + (size_t)blk * SS;
    const __nv_bfloat16* rel = el + (size_t)blk * SS;
    float* row = attn + (size_t)blk * SS;
    const int limit = ((s >> 7) + 1) * 128;
    for (int j = threadIdx.x * 4; j < limit; j += 1024) {
        const __nv_bfloat162 h2 = *(const __nv_bfloat162*)(reh + j);
        const __nv_bfloat162 h3 = *(const __nv_bfloat162*)(reh + j + 2);
        const __nv_bfloat162 l2 = *(const __nv_bfloat162*)(rel + j);
        const __nv_bfloat162 l3 = *(const __nv_bfloat162*)(rel + j + 2);
        float4 o;
        o.x = (__bfloat162float(h2.x) + __bfloat162float(l2.x)) * inv;
        o.y = (__bfloat162float(h2.y) + __bfloat162float(l2.y)) * inv;
        o.z = (__bfloat162float(h3.x) + __bfloat162float(l3.x)) * inv;
        o.w = (__bfloat162float(h3.y) + __bfloat162float(l3.y)) * inv;
        *(float4*)(row + j) = o;
    }
}

// ---------------------------------------------------------------------------
// Transpose V per head into bf16 hi/lo planes: vt[bh][d][s]
// ---------------------------------------------------------------------------
__global__ __launch_bounds__(256) void transpose_v(
    const float* __restrict__ v,
    __nv_bfloat16* __restrict__ vth, __nv_bfloat16* __restrict__ vtl)
{
    __shared__ float t[32][33];
    const int bh = blockIdx.z, b = bh / HH, h = bh % HH;
    const int s0 = blockIdx.x * 32, d0 = blockIdx.y * 32;
    const int tx = threadIdx.x & 31, ty = threadIdx.x >> 5;
    #pragma unroll
    for (int i = 0; i < 4; i++)
        t[ty + i * 8][tx] =
            v[(size_t)(b * SS + s0 + ty + i * 8) * DD + h * DK + d0 + tx];
    __syncthreads();
    #pragma unroll
    for (int i = 0; i < 4; i++) {
        const float f = t[tx][ty + i * 8];
        const __nv_bfloat16 hh = __float2bfloat16_rn(f);
        const __nv_bfloat16 ll = __float2bfloat16_rn(f - __bfloat162float(hh));
        const size_t idx = (size_t)bh * DK * SS + (size_t)(d0 + ty + i * 8) * SS
                         + s0 + tx;
        vth[idx] = hh;
        vtl[idx] = ll;
    }
}

// ---------------------------------------------------------------------------
// AV (v6 core, 128 threads): x = (E @ V) * inv; heavy-first 1D grid.
// ---------------------------------------------------------------------------
__global__ void av_mma_kernel(
    const __nv_bfloat16* __restrict__ eh, const __nv_bfloat16* __restrict__ el,
    const __nv_bfloat16* __restrict__ vth, const __nv_bfloat16* __restrict__ vtl,
    const float* __restrict__ ginv,
    __nv_bfloat16* __restrict__ xh, __nv_bfloat16* __restrict__ xl)
{
    const int t = blockIdx.x;              // 0..511, heavy bm first
    const int bm = 15 - (t >> 5);
    const int bh = t & 31;
    extern __shared__ char dsm[];
    const uint32_t sbase = smem_u32(dsm);
    const int b = bh / HH, h = bh % HH;
    const int tid  = threadIdx.x;
    const int lane = tid & 31;
    const int wid  = tid >> 5;
    const int wm   = wid >> 1;
    const int wn   = wid & 1;

    const size_t aoff = (size_t)bh * SS * SS + (size_t)(bm * 128) * SS;
    const size_t boff = (size_t)bh * DK * SS;

    MmaB16v6 core;
    core.run(sbase, eh + aoff, el + aoff, SS, vth + boff, vtl + boff, SS,
             (bm + 1) * 8, tid);

    #pragma unroll
    for (int mt = 0; mt < 4; mt++) {
        const int row = bm * 128 + wm * 64 + mt * 16 + (lane >> 2);
        const float inv0 = ginv[(size_t)bh * SS + row];
        const float inv1 = ginv[(size_t)bh * SS + row + 8];
        #pragma unroll
        for (int nt = 0; nt < 8; nt++) {
            const int col = wn * 64 + nt * 8 + (lane & 3) * 2;
            const float v0 = core.acc[mt][nt][0] * inv0;
            const float v1 = core.acc[mt][nt][1] * inv0;
            const float v2 = core.acc[mt][nt][2] * inv1;
            const float v3 = core.acc[mt][nt][3] * inv1;
            __nv_bfloat16 h0 = __float2bfloat16_rn(v0);
            __nv_bfloat16 h1 = __float2bfloat16_rn(v1);
            __nv_bfloat16 h2 = __float2bfloat16_rn(v2);
            __nv_bfloat16 h3 = __float2bfloat16_rn(v3);
            const size_t o0 = (size_t)(b * SS + row) * DD + h * DK + col;
            const size_t o1 = (size_t)(b * SS + row + 8) * DD + h * DK + col;
            *(uint32_t*)(xh + o0) = pack_bf2(h0, h1);
            *(uint32_t*)(xl + o0) = pack_bf2(
                __float2bfloat16_rn(v0 - __bfloat162float(h0)),
                __float2bfloat16_rn(v1 - __bfloat162float(h1)));
            *(uint32_t*)(xh + o1) = pack_bf2(h2, h3);
            *(uint32_t*)(xl + o1) = pack_bf2(
                __float2bfloat16_rn(v2 - __bfloat162float(h2)),
                __float2bfloat16_rn(v3 - __bfloat162float(h3)));
        }
    }
}

// ---------------------------------------------------------------------------
extern "C" void kernel_launch(void* const* d_in, const int* in_sizes, int n_in,
                              void* d_out, int out_size)
{
    const float* query = (const float*)d_in[0];
    const float* key   = (const float*)d_in[1];
    const float* value = (const float*)d_in[2];
    const float* Wq = (const float*)d_in[3];
    const float* bq = (const float*)d_in[4];
    const float* Wk = (const float*)d_in[5];
    const float* bk = (const float*)d_in[6];
    const float* Wv = (const float*)d_in[7];
    const float* bv = (const float*)d_in[8];
    const float* Wo = (const float*)d_in[9];
    const float* bo = (const float*)d_in[10];

    float* out  = (float*)d_out;                       // [4096, 2048]
    float* attn = out + (size_t)MTOK * DD;             // [32, 2048, 2048]

    float *v, *rpart, *ginv;
    __nv_bfloat16 *qih, *qil, *kih, *kil, *vih, *vil, *wh, *wl;
    __nv_bfloat16 *qh, *ql, *kh, *kl, *xh, *xl, *vth, *vtl, *eh, *el;
    cudaGetSymbolAddress((void**)&v, g_v);
    cudaGetSymbolAddress((void**)&rpart, g_rpart);
    cudaGetSymbolAddress((void**)&ginv, g_inv);
    cudaGetSymbolAddress((void**)&qih, g_qih);
    cudaGetSymbolAddress((void**)&qil, g_qil);
    cudaGetSymbolAddress((void**)&kih, g_kih);
    cudaGetSymbolAddress((void**)&kil, g_kil);
    cudaGetSymbolAddress((void**)&vih, g_vih);
    cudaGetSymbolAddress((void**)&vil, g_vil);
    cudaGetSymbolAddress((void**)&wh, g_wh);
    cudaGetSymbolAddress((void**)&wl, g_wl);
    cudaGetSymbolAddress((void**)&qh, g_qh);
    cudaGetSymbolAddress((void**)&ql, g_ql);
    cudaGetSymbolAddress((void**)&kh, g_kh);
    cudaGetSymbolAddress((void**)&kl, g_kl);
    cudaGetSymbolAddress((void**)&xh, g_xh);
    cudaGetSymbolAddress((void**)&xl, g_xl);
    cudaGetSymbolAddress((void**)&vth, g_vth);
    cudaGetSymbolAddress((void**)&vtl, g_vtl);
    cudaGetSymbolAddress((void**)&eh, g_eh);
    cudaGetSymbolAddress((void**)&el, g_el);

    static cudaStream_t s1 = nullptr;
    static cudaEvent_t evA = nullptr, evB = nullptr, evF = nullptr;
    static cudaEvent_t evP = nullptr, evT = nullptr;
    if (s1 == nullptr) {
        cudaStreamCreateWithFlags(&s1, cudaStreamNonBlocking);
        cudaEventCreateWithFlags(&evA, cudaEventDisableTiming);
        cudaEventCreateWithFlags(&evB, cudaEventDisableTiming);
        cudaEventCreateWithFlags(&evF, cudaEventDisableTiming);
        cudaEventCreateWithFlags(&evP, cudaEventDisableTiming);
        cudaEventCreateWithFlags(&evT, cudaEventDisableTiming);
        cudaFuncSetAttribute(proj_qkv,
            cudaFuncAttributeMaxDynamicSharedMemorySize, DSMEM_V6);
        cudaFuncSetAttribute(gemm_b16,
            cudaFuncAttributeMaxDynamicSharedMemorySize, DSMEM_V6);
        cudaFuncSetAttribute(scores_exp_kernel,
            cudaFuncAttributeMaxDynamicSharedMemorySize, DSMEM_V6);
        cudaFuncSetAttribute(av_mma_kernel,
            cudaFuncAttributeMaxDynamicSharedMemorySize, DSMEM_V6);
    }

    // Fork side stream: zero the above-diagonal attn tail (no dependencies)
    cudaEventRecord(evA, 0);
    cudaStreamWaitEvent(s1, evA, 0);
    zero_tail<<<BB * HH * SS, 256, 0, s1>>>(attn);

    // Main stream: splits -> proj
    dim3 gsi((MTOK * DD) / (256 * 4), 3);
    split_inputs<<<gsi, 256>>>(query, key, value,
                               qih, qil, kih, kil, vih, vil);
    dim3 gsw((DD * DD) / (256 * 4), 4);
    split_weights<<<gsw, 256>>>(Wq, Wk, Wv, Wo, wh, wl);

    dim3 gproj(DD / 128, MTOK / 128, 3);                // (16, 32, 3)
    proj_qkv<<<gproj, 128, DSMEM_V6>>>(
        qih, qil, kih, kil, vih, vil, wh, wl, bq, bk, bv,
        qh, ql, kh, kl, v);

    // Side stream: V transpose (scores doesn't need it; AV does)
    cudaEventRecord(evP, 0);
    cudaStreamWaitEvent(s1, evP, 0);
    dim3 gtr(SS / 32, DK / 32, BB * HH);
    transpose_v<<<gtr, 256, 0, s1>>>(v, vth, vtl);
    cudaEventRecord(evT, s1);

    // Main stream: scores -> ginv
    dim3 gsc(136, BB * HH);
    scores_exp_kernel<<<gsc, 128, DSMEM_V6>>>(qh, ql, kh, kl, eh, el, rpart);

    ginv_kernel<<<(BB * HH * SS) / 256, 256>>>(rpart, ginv);

    // Side stream: finalize attn prefix (overlaps AV + output projection)
    cudaEventRecord(evB, 0);
    cudaStreamWaitEvent(s1, evB, 0);
    finalize_prefix<<<BB * HH * SS, 256, 0, s1>>>(eh, el, ginv, attn);
    cudaEventRecord(evF, s1);

    // Main stream: AV (needs vt from side stream), output projection
    cudaStreamWaitEvent(0, evT, 0);
    av_mma_kernel<<<512, 128, DSMEM_V6>>>(eh, el, vth, vtl, ginv, xh, xl);

    dim3 gout(DD / 128, MTOK / 128);                    // (16, 32)
    gemm_b16<<<gout, 128, DSMEM_V6>>>(
        xh, xl, wh + (size_t)3 * DD * DD, wl + (size_t)3 * DD * DD, bo, out);

    // Join side stream into the graph
    cudaStreamWaitEvent(0, evF, 0);
}

// round 17
// speedup vs baseline: 1.3523x; 1.0175x over previous
#include <cuda_runtime.h>
#include <cuda_bf16.h>
#include <cstdint>
#include <math.h>

// ---------------------------------------------------------------------------
// Problem constants
// ---------------------------------------------------------------------------
#define BB   2
#define SS   2048
#define DD   2048
#define HH   16
#define DK   128
#define MTOK (BB * SS)          // 4096 tokens
#define SCALE 0.08838834764831845f  // 1/sqrt(128)

// Scratch (device globals; no cudaMalloc allowed)
static __device__ float g_v [(size_t)MTOK * DD];
static __device__ float g_rpart[(size_t)BB * HH * SS * 16];
static __device__ float g_inv[(size_t)BB * HH * SS];
// bf16 hi/lo planes
static __device__ __nv_bfloat16 g_qih[(size_t)MTOK * DD], g_qil[(size_t)MTOK * DD];
static __device__ __nv_bfloat16 g_kih[(size_t)MTOK * DD], g_kil[(size_t)MTOK * DD];
static __device__ __nv_bfloat16 g_vih[(size_t)MTOK * DD], g_vil[(size_t)MTOK * DD];
static __device__ __nv_bfloat16 g_wh[(size_t)4 * DD * DD], g_wl[(size_t)4 * DD * DD];
static __device__ __nv_bfloat16 g_qh[(size_t)MTOK * DD], g_ql[(size_t)MTOK * DD];
static __device__ __nv_bfloat16 g_kh[(size_t)MTOK * DD], g_kl[(size_t)MTOK * DD];
static __device__ __nv_bfloat16 g_xh[(size_t)MTOK * DD], g_xl[(size_t)MTOK * DD];
static __device__ __nv_bfloat16 g_vth[(size_t)BB * HH * DK * SS];
static __device__ __nv_bfloat16 g_vtl[(size_t)BB * HH * DK * SS];
// Unnormalized-E planes
static __device__ __nv_bfloat16 g_eh[(size_t)BB * HH * SS * SS];
static __device__ __nv_bfloat16 g_el[(size_t)BB * HH * SS * SS];

// ---------------------------------------------------------------------------
// PTX helpers
// ---------------------------------------------------------------------------
#define LDSM_X4(r0, r1, r2, r3, addr) \
    asm volatile("ldmatrix.sync.aligned.m8n8.x4.shared.b16 {%0,%1,%2,%3}, [%4];" \
        : "=r"(r0), "=r"(r1), "=r"(r2), "=r"(r3) : "r"(addr))

#define MMA16816(c, a0, a1, a2, a3, b0, b1) \
    asm volatile("mma.sync.aligned.m16n8k16.row.col.f32.bf16.bf16.f32 " \
        "{%0,%1,%2,%3}, {%4,%5,%6,%7}, {%8,%9}, {%0,%1,%2,%3};" \
        : "+f"((c)[0]), "+f"((c)[1]), "+f"((c)[2]), "+f"((c)[3]) \
        : "r"(a0), "r"(a1), "r"(a2), "r"(a3), "r"(b0), "r"(b1))

#define CP16(dst, src) \
    asm volatile("cp.async.cg.shared.global [%0], [%1], 16;" \
        :: "r"(dst), "l"(src))
#define CPCOMMIT() asm volatile("cp.async.commit_group;" ::: "memory")
#define CPWAIT2()  asm volatile("cp.async.wait_group 2;" ::: "memory")

__device__ __forceinline__ uint32_t smem_u32(const void* p) {
    uint32_t a;
    asm("{ .reg .u64 t; cvta.to.shared.u64 t, %1; cvt.u32.u64 %0, t; }"
        : "=r"(a) : "l"(p));
    return a;
}

__device__ __forceinline__ uint32_t pack_bf2(__nv_bfloat16 a, __nv_bfloat16 b) {
    return (uint32_t)__bfloat16_as_ushort(a) |
           ((uint32_t)__bfloat16_as_ushort(b) << 16);
}

__device__ __forceinline__ void split4(const float4 f, uint2& hi, uint2& lo) {
    __nv_bfloat16 h0 = __float2bfloat16_rn(f.x);
    __nv_bfloat16 h1 = __float2bfloat16_rn(f.y);
    __nv_bfloat16 h2 = __float2bfloat16_rn(f.z);
    __nv_bfloat16 h3 = __float2bfloat16_rn(f.w);
    __nv_bfloat16 l0 = __float2bfloat16_rn(f.x - __bfloat162float(h0));
    __nv_bfloat16 l1 = __float2bfloat16_rn(f.y - __bfloat162float(h1));
    __nv_bfloat16 l2 = __float2bfloat16_rn(f.z - __bfloat162float(h2));
    __nv_bfloat16 l3 = __float2bfloat16_rn(f.w - __bfloat162float(h3));
    hi.x = pack_bf2(h0, h1); hi.y = pack_bf2(h2, h3);
    lo.x = pack_bf2(l0, l1); lo.y = pack_bf2(l2, l3);
}

#define RS2 48
#define NS 4
#define ST_AHI 0
#define ST_ALO 6144
#define ST_BHI 12288
#define ST_BLO 18432
#define ST_BYTES 24576
#define DSMEM_V6 (NS * ST_BYTES)   // 98304

// ---------------------------------------------------------------------------
// MmaB16v6r: 128x128 tile, 128 threads (4 warps, 64x64 warp tile),
// K-chunk 16, 4-stage cp.async pipeline, 2 CTAs/SM, natural regs (~198).
// R17 change vs R13: next-stage cp.async issue hoisted BETWEEN the LDSM block
// and the MMA block (safe: top-of-stage barrier already covers the
// write-after-read hazard on buffer (s-1)%NS). Starts global loads ~860cy
// earlier and removes LSU issue from the post-MMA critical path.
// ---------------------------------------------------------------------------
struct MmaB16v6 {
    float acc[4][8][4];

    __device__ __forceinline__ static void issue(
        uint32_t sb,
        const __nv_bfloat16* Ah, const __nv_bfloat16* Al, size_t sA,
        const __nv_bfloat16* Bh, const __nv_bfloat16* Bl, size_t sB,
        int k0, int tid)
    {
        const int r0   = tid >> 1;
        const int half = tid & 1;
        #pragma unroll
        for (int p = 0; p < 2; p++) {
            const int r = r0 + p * 64;
            const uint32_t so = (uint32_t)r * RS2 + half * 16;
            const size_t oA = (size_t)r * sA + k0 + half * 8;
            const size_t oB = (size_t)r * sB + k0 + half * 8;
            CP16(sb + ST_AHI + so, Ah + oA);
            CP16(sb + ST_ALO + so, Al + oA);
            CP16(sb + ST_BHI + so, Bh + oB);
            CP16(sb + ST_BLO + so, Bl + oB);
        }
    }

    __device__ __forceinline__ void run(
        uint32_t sbase,
        const __nv_bfloat16* Ah, const __nv_bfloat16* Al, size_t sA,
        const __nv_bfloat16* Bh, const __nv_bfloat16* Bl, size_t sB,
        const int nIter, const int tid)
    {
        const int lane = tid & 31;
        const int wid  = tid >> 5;
        const int wm   = wid >> 1;
        const int wn   = wid & 1;

        #pragma unroll
        for (int i = 0; i < 4; i++)
            #pragma unroll
            for (int j = 0; j < 8; j++)
                #pragma unroll
                for (int c = 0; c < 4; c++) acc[i][j][c] = 0.0f;

        const uint32_t aAddr = sbase + ST_AHI
            + (uint32_t)(wm * 64 + (lane & 15)) * RS2 + (lane >> 4) * 16;
        const uint32_t bAddr = sbase + ST_BHI
            + (uint32_t)(wn * 64 + (lane & 7) + ((lane >> 4) & 1) * 8) * RS2
            + ((lane >> 3) & 1) * 16;

        #pragma unroll
        for (int p = 0; p < NS - 1; p++) {
            if (p < nIter)
                issue(sbase + p * ST_BYTES, Ah, Al, sA, Bh, Bl, sB, p * 16, tid);
            CPCOMMIT();
        }

        for (int s = 0; s < nIter; s++) {
            CPWAIT2();
            __syncthreads();

            const uint32_t bo = (uint32_t)(s & (NS - 1)) * ST_BYTES;
            uint32_t ahi[4][4], alo[4][4];
            uint32_t bhi[4][4], blo[4][4];
            #pragma unroll
            for (int mt = 0; mt < 4; mt++) {
                const uint32_t a = aAddr + bo + mt * (16 * RS2);
                LDSM_X4(ahi[mt][0], ahi[mt][1], ahi[mt][2], ahi[mt][3], a);
                LDSM_X4(alo[mt][0], alo[mt][1], alo[mt][2], alo[mt][3],
                        a + (ST_ALO - ST_AHI));
            }
            #pragma unroll
            for (int nq = 0; nq < 4; nq++) {
                const uint32_t b = bAddr + bo + nq * (16 * RS2);
                LDSM_X4(bhi[nq][0], bhi[nq][1], bhi[nq][2], bhi[nq][3], b);
                LDSM_X4(blo[nq][0], blo[nq][1], blo[nq][2], blo[nq][3],
                        b + (ST_BLO - ST_BHI));
            }

            // Hoisted issue: start stage s+3's global loads before the MMAs.
            // Barrier at top of this stage already guarantees all warps
            // finished their LDSMs of buffer (s-1)%NS == (s+NS-1)%NS.
            const int nx = s + NS - 1;
            if (nx < nIter)
                issue(sbase + (uint32_t)(nx & (NS - 1)) * ST_BYTES,
                      Ah, Al, sA, Bh, Bl, sB, nx * 16, tid);
            CPCOMMIT();

            #pragma unroll
            for (int mt = 0; mt < 4; mt++)
                #pragma unroll
                for (int nq = 0; nq < 4; nq++)
                    #pragma unroll
                    for (int t = 0; t < 2; t++)
                        MMA16816(acc[mt][nq * 2 + t],
                                 ahi[mt][0], ahi[mt][1], ahi[mt][2], ahi[mt][3],
                                 bhi[nq][t * 2], bhi[nq][t * 2 + 1]);
            #pragma unroll
            for (int mt = 0; mt < 4; mt++)
                #pragma unroll
                for (int nq = 0; nq < 4; nq++)
                    #pragma unroll
                    for (int t = 0; t < 2; t++)
                        MMA16816(acc[mt][nq * 2 + t],
                                 ahi[mt][0], ahi[mt][1], ahi[mt][2], ahi[mt][3],
                                 blo[nq][t * 2], blo[nq][t * 2 + 1]);
            #pragma unroll
            for (int mt = 0; mt < 4; mt++)
                #pragma unroll
                for (int nq = 0; nq < 4; nq++)
                    #pragma unroll
                    for (int t = 0; t < 2; t++)
                        MMA16816(acc[mt][nq * 2 + t],
                                 alo[mt][0], alo[mt][1], alo[mt][2], alo[mt][3],
                                 bhi[nq][t * 2], bhi[nq][t * 2 + 1]);
        }
        __syncthreads();
    }
};

// ---------------------------------------------------------------------------
// Split fp32 tensors into bf16 hi/lo planes
// ---------------------------------------------------------------------------
__global__ __launch_bounds__(256) void split_inputs(
    const float* __restrict__ a0, const float* __restrict__ a1,
    const float* __restrict__ a2,
    __nv_bfloat16* __restrict__ h0, __nv_bfloat16* __restrict__ l0,
    __nv_bfloat16* __restrict__ h1, __nv_bfloat16* __restrict__ l1,
    __nv_bfloat16* __restrict__ h2, __nv_bfloat16* __restrict__ l2)
{
    const int z = blockIdx.y;
    const float* s = (z == 0) ? a0 : (z == 1) ? a1 : a2;
    __nv_bfloat16* H = (z == 0) ? h0 : (z == 1) ? h1 : h2;
    __nv_bfloat16* L = (z == 0) ? l0 : (z == 1) ? l1 : l2;
    const size_t i = ((size_t)blockIdx.x * 256 + threadIdx.x) * 4;
    float4 f = *(const float4*)(s + i);
    uint2 hi, lo;
    split4(f, hi, lo);
    *(uint2*)(H + i) = hi;
    *(uint2*)(L + i) = lo;
}

__global__ __launch_bounds__(256) void split_weights(
    const float* __restrict__ w0, const float* __restrict__ w1,
    const float* __restrict__ w2, const float* __restrict__ w3,
    __nv_bfloat16* __restrict__ wh, __nv_bfloat16* __restrict__ wl)
{
    const int z = blockIdx.y;
    const float* s = (z == 0) ? w0 : (z == 1) ? w1 : (z == 2) ? w2 : w3;
    const size_t base = (size_t)z * DD * DD;
    const size_t i = ((size_t)blockIdx.x * 256 + threadIdx.x) * 4;
    float4 f = *(const float4*)(s + i);
    uint2 hi, lo;
    split4(f, hi, lo);
    *(uint2*)(wh + base + i) = hi;
    *(uint2*)(wl + base + i) = lo;
}

// ---------------------------------------------------------------------------
// Batched Q/K/V projection (v6 core, 128 threads)
// ---------------------------------------------------------------------------
__global__ void proj_qkv(
    const __nv_bfloat16* __restrict__ qih, const __nv_bfloat16* __restrict__ qil,
    const __nv_bfloat16* __restrict__ kih, const __nv_bfloat16* __restrict__ kil,
    const __nv_bfloat16* __restrict__ vih, const __nv_bfloat16* __restrict__ vil,
    const __nv_bfloat16* __restrict__ wh, const __nv_bfloat16* __restrict__ wl,
    const float* __restrict__ bq, const float* __restrict__ bk,
    const float* __restrict__ bv,
    __nv_bfloat16* __restrict__ qh, __nv_bfloat16* __restrict__ ql,
    __nv_bfloat16* __restrict__ kh, __nv_bfloat16* __restrict__ kl,
    float* __restrict__ v)
{
    extern __shared__ char dsm[];
    const uint32_t sbase = smem_u32(dsm);
    const int tid  = threadIdx.x;
    const int lane = tid & 31;
    const int wid  = tid >> 5;
    const int wm   = wid >> 1;
    const int wn   = wid & 1;
    const int bn   = blockIdx.x;
    const int bm   = blockIdx.y;
    const int z    = blockIdx.z;

    const __nv_bfloat16* Ah = (z == 0) ? qih : (z == 1) ? kih : vih;
    const __nv_bfloat16* Al = (z == 0) ? qil : (z == 1) ? kil : vil;
    const float* bias = (z == 0) ? bq : (z == 1) ? bk : bv;
    const size_t wbase = (size_t)z * DD * DD;

    MmaB16v6 core;
    core.run(sbase,
             Ah + (size_t)(bm * 128) * DD, Al + (size_t)(bm * 128) * DD, DD,
             wh + wbase + (size_t)(bn * 128) * DD,
             wl + wbase + (size_t)(bn * 128) * DD, DD,
             DD / 16, tid);

    #pragma unroll
    for (int mt = 0; mt < 4; mt++) {
        const int row = bm * 128 + wm * 64 + mt * 16 + (lane >> 2);
        #pragma unroll
        for (int nt = 0; nt < 8; nt++) {
            const int col = bn * 128 + wn * 64 + nt * 8 + (lane & 3) * 2;
            const float b0 = bias[col], b1 = bias[col + 1];
            const float v0 = core.acc[mt][nt][0] + b0;
            const float v1 = core.acc[mt][nt][1] + b1;
            const float v2 = core.acc[mt][nt][2] + b0;
            const float v3 = core.acc[mt][nt][3] + b1;
            if (z == 2) {
                *(float2*)(v + (size_t)row * DD + col) = make_float2(v0, v1);
                *(float2*)(v + (size_t)(row + 8) * DD + col) = make_float2(v2, v3);
            } else {
                __nv_bfloat16* H = (z == 0) ? qh : kh;
                __nv_bfloat16* L = (z == 0) ? ql : kl;
                __nv_bfloat16 h0 = __float2bfloat16_rn(v0);
                __nv_bfloat16 h1 = __float2bfloat16_rn(v1);
                __nv_bfloat16 h2 = __float2bfloat16_rn(v2);
                __nv_bfloat16 h3 = __float2bfloat16_rn(v3);
                *(uint32_t*)(H + (size_t)row * DD + col) = pack_bf2(h0, h1);
                *(uint32_t*)(L + (size_t)row * DD + col) = pack_bf2(
                    __float2bfloat16_rn(v0 - __bfloat162float(h0)),
                    __float2bfloat16_rn(v1 - __bfloat162float(h1)));
                *(uint32_t*)(H + (size_t)(row + 8) * DD + col) = pack_bf2(h2, h3);
                *(uint32_t*)(L + (size_t)(row + 8) * DD + col) = pack_bf2(
                    __float2bfloat16_rn(v2 - __bfloat162float(h2)),
                    __float2bfloat16_rn(v3 - __bfloat162float(h3)));
            }
        }
    }
}

// ---------------------------------------------------------------------------
// Final GEMM (v6 core): out = x @ Wo^T + bo
// ---------------------------------------------------------------------------
__global__ void gemm_b16(
    const __nv_bfloat16* __restrict__ Ah, const __nv_bfloat16* __restrict__ Al,
    const __nv_bfloat16* __restrict__ Wh, const __nv_bfloat16* __restrict__ Wl,
    const float* __restrict__ bias, float* __restrict__ C)
{
    extern __shared__ char dsm[];
    const uint32_t sbase = smem_u32(dsm);
    const int tid  = threadIdx.x;
    const int lane = tid & 31;
    const int wid  = tid >> 5;
    const int wm   = wid >> 1;
    const int wn   = wid & 1;
    const int bn   = blockIdx.x;
    const int bm   = blockIdx.y;

    MmaB16v6 core;
    core.run(sbase,
             Ah + (size_t)(bm * 128) * DD, Al + (size_t)(bm * 128) * DD, DD,
             Wh + (size_t)(bn * 128) * DD, Wl + (size_t)(bn * 128) * DD, DD,
             DD / 16, tid);

    #pragma unroll
    for (int mt = 0; mt < 4; mt++) {
        const int row = bm * 128 + wm * 64 + mt * 16 + (lane >> 2);
        #pragma unroll
        for (int nt = 0; nt < 8; nt++) {
            const int col = bn * 128 + wn * 64 + nt * 8 + (lane & 3) * 2;
            const float b0 = bias[col], b1 = bias[col + 1];
            float2 o0, o1;
            o0.x = core.acc[mt][nt][0] + b0; o0.y = core.acc[mt][nt][1] + b1;
            o1.x = core.acc[mt][nt][2] + b0; o1.y = core.acc[mt][nt][3] + b1;
            *(float2*)(C + (size_t)row * DD + col) = o0;
            *(float2*)(C + (size_t)(row + 8) * DD + col) = o1;
        }
    }
}

// ---------------------------------------------------------------------------
// Scores+exp (v6 core, 128 threads): triangular grid; E planes + partials.
// ---------------------------------------------------------------------------
__global__ void scores_exp_kernel(
    const __nv_bfloat16* __restrict__ qh, const __nv_bfloat16* __restrict__ ql,
    const __nv_bfloat16* __restrict__ kh, const __nv_bfloat16* __restrict__ kl,
    __nv_bfloat16* __restrict__ eh, __nv_bfloat16* __restrict__ el,
    float* __restrict__ rpart)
{
    const int idx = blockIdx.x;            // 0..135 (lower-triangle tile id)
    int bm = (int)((sqrtf(8.f * idx + 1.f) - 1.f) * 0.5f);
    while ((bm + 1) * (bm + 2) / 2 <= idx) bm++;
    while (bm * (bm + 1) / 2 > idx) bm--;
    const int bn = idx - bm * (bm + 1) / 2;
    const int bh = blockIdx.y;
    const int tid = threadIdx.x;

    extern __shared__ char dsm[];
    __shared__ float rs[128][2];
    const uint32_t sbase = smem_u32(dsm);
    const int lane = tid & 31;
    const int wid  = tid >> 5;
    const int wm   = wid >> 1;
    const int wn   = wid & 1;
    const int b = bh / HH, h = bh % HH;

    const size_t aoff = (size_t)(b * SS + bm * 128) * DD + h * DK;
    const size_t boff = (size_t)(b * SS + bn * 128) * DD + h * DK;

    MmaB16v6 core;
    core.run(sbase, qh + aoff, ql + aoff, DD, kh + boff, kl + boff, DD,
             DK / 16, tid);

    __nv_bfloat16* peh = eh + (size_t)bh * SS * SS;
    __nv_bfloat16* pel = el + (size_t)bh * SS * SS;

    float rsum[4][2];
    #pragma unroll
    for (int mt = 0; mt < 4; mt++) { rsum[mt][0] = 0.f; rsum[mt][1] = 0.f; }

    #pragma unroll
    for (int mt = 0; mt < 4; mt++) {
        const int r0 = bm * 128 + wm * 64 + mt * 16 + (lane >> 2);
        const int r1 = r0 + 8;
        #pragma unroll
        for (int nt = 0; nt < 8; nt++) {
            const int col = bn * 128 + wn * 64 + nt * 8 + (lane & 3) * 2;
            float e0 = (col     <= r0) ? __expf(core.acc[mt][nt][0] * SCALE) : 0.f;
            float e1 = (col + 1 <= r0) ? __expf(core.acc[mt][nt][1] * SCALE) : 0.f;
            float e2 = (col     <= r1) ? __expf(core.acc[mt][nt][2] * SCALE) : 0.f;
            float e3 = (col + 1 <= r1) ? __expf(core.acc[mt][nt][3] * SCALE) : 0.f;
            rsum[mt][0] += e0 + e1;
            rsum[mt][1] += e2 + e3;
            __nv_bfloat16 h0 = __float2bfloat16_rn(e0);
            __nv_bfloat16 h1 = __float2bfloat16_rn(e1);
            __nv_bfloat16 h2 = __float2bfloat16_rn(e2);
            __nv_bfloat16 h3 = __float2bfloat16_rn(e3);
            *(uint32_t*)(peh + (size_t)r0 * SS + col) = pack_bf2(h0, h1);
            *(uint32_t*)(pel + (size_t)r0 * SS + col) = pack_bf2(
                __float2bfloat16_rn(e0 - __bfloat162float(h0)),
                __float2bfloat16_rn(e1 - __bfloat162float(h1)));
            *(uint32_t*)(peh + (size_t)r1 * SS + col) = pack_bf2(h2, h3);
            *(uint32_t*)(pel + (size_t)r1 * SS + col) = pack_bf2(
                __float2bfloat16_rn(e2 - __bfloat162float(h2)),
                __float2bfloat16_rn(e3 - __bfloat162float(h3)));
        }
    }

    #pragma unroll
    for (int mt = 0; mt < 4; mt++) {
        #pragma unroll
        for (int hf = 0; hf < 2; hf++) {
            float vv = rsum[mt][hf];
            vv += __shfl_xor_sync(0xffffffffu, vv, 1);
            vv += __shfl_xor_sync(0xffffffffu, vv, 2);
            if ((lane & 3) == 0) {
                const int lrow = wm * 64 + mt * 16 + hf * 8 + (lane >> 2);
                rs[lrow][wn] = vv;
            }
        }
    }
    __syncthreads();
    const float p = rs[tid][0] + rs[tid][1];
    rpart[((size_t)bh * SS + bm * 128 + tid) * 16 + bn] = p;
}

// ---------------------------------------------------------------------------
// ginv: 1/rowsum from partials
// ---------------------------------------------------------------------------
__global__ __launch_bounds__(256) void ginv_kernel(
    const float* __restrict__ rpart, float* __restrict__ ginv)
{
    const int i = blockIdx.x * 256 + threadIdx.x;   // bh*SS + s
    const int s = i & (SS - 1);
    const float* p = rpart + (size_t)i * 16;
    const int nb = (s >> 7) + 1;
    float sum = 0.f;
    for (int k = 0; k < nb; k++) sum += p[k];
    ginv[i] = 1.0f / sum;
}

// ---------------------------------------------------------------------------
// Zero the above-diagonal tail of attn (side stream)
// ---------------------------------------------------------------------------
__global__ __launch_bounds__(256) void zero_tail(float* __restrict__ attn)
{
    const int blk = blockIdx.x;           // bh*SS + s
    const int s   = blk & (SS - 1);
    const int limit = ((s >> 7) + 1) * 128;
    float* row = attn + (size_t)blk * SS;
    const float4 z = make_float4(0.f, 0.f, 0.f, 0.f);
    for (int j = limit + threadIdx.x * 4; j < SS; j += 1024)
        *(float4*)(row + j) = z;
}

// ---------------------------------------------------------------------------
// Finalize (prefix only): attn[0..limit) = (Eh+El)*inv. Tail pre-zeroed.
// ---------------------------------------------------------------------------
__global__ __launch_bounds__(256) void finalize_prefix(
    const __nv_bfloat16* __restrict__ eh, const __nv_bfloat16* __restrict__ el,
    const float* __restrict__ ginv, float* __restrict__ attn)
{
    const int blk = blockIdx.x;           // bh*SS + s
    const int s   = blk & (SS - 1);
    const float inv = ginv[blk];
    const __nv_bfloat16* reh = eh + (size_t)blk * SS;
    const __nv_bfloat16* rel = el + (size_t)blk * SS;
    float* row = attn + (size_t)blk * SS;
    const int limit = ((s >> 7) + 1) * 128;
    for (int j = threadIdx.x * 4; j < limit; j += 1024) {
        const __nv_bfloat162 h2 = *(const __nv_bfloat162*)(reh + j);
        const __nv_bfloat162 h3 = *(const __nv_bfloat162*)(reh + j + 2);
        const __nv_bfloat162 l2 = *(const __nv_bfloat162*)(rel + j);
        const __nv_bfloat162 l3 = *(const __nv_bfloat162*)(rel + j + 2);
        float4 o;
        o.x = (__bfloat162float(h2.x) + __bfloat162float(l2.x)) * inv;
        o.y = (__bfloat162float(h2.y) + __bfloat162float(l2.y)) * inv;
        o.z = (__bfloat162float(h3.x) + __bfloat162float(l3.x)) * inv;
        o.w = (__bfloat162float(h3.y) + __bfloat162float(l3.y)) * inv;
        *(float4*)(row + j) = o;
    }
}

// ---------------------------------------------------------------------------
// Transpose V per head into bf16 hi/lo planes: vt[bh][d][s]
// ---------------------------------------------------------------------------
__global__ __launch_bounds__(256) void transpose_v(
    const float* __restrict__ v,
    __nv_bfloat16* __restrict__ vth, __nv_bfloat16* __restrict__ vtl)
{
    __shared__ float t[32][33];
    const int bh = blockIdx.z, b = bh / HH, h = bh % HH;
    const int s0 = blockIdx.x * 32, d0 = blockIdx.y * 32;
    const int tx = threadIdx.x & 31, ty = threadIdx.x >> 5;
    #pragma unroll
    for (int i = 0; i < 4; i++)
        t[ty + i * 8][tx] =
            v[(size_t)(b * SS + s0 + ty + i * 8) * DD + h * DK + d0 + tx];
    __syncthreads();
    #pragma unroll
    for (int i = 0; i < 4; i++) {
        const float f = t[tx][ty + i * 8];
        const __nv_bfloat16 hh = __float2bfloat16_rn(f);
        const __nv_bfloat16 ll = __float2bfloat16_rn(f - __bfloat162float(hh));
        const size_t idx = (size_t)bh * DK * SS + (size_t)(d0 + ty + i * 8) * SS
                         + s0 + tx;
        vth[idx] = hh;
        vtl[idx] = ll;
    }
}

// ---------------------------------------------------------------------------
// AV (v6 core, 128 threads): x = (E @ V) * inv; heavy-first 1D grid.
// ---------------------------------------------------------------------------
__global__ void av_mma_kernel(
    const __nv_bfloat16* __restrict__ eh, const __nv_bfloat16* __restrict__ el,
    const __nv_bfloat16* __restrict__ vth, const __nv_bfloat16* __restrict__ vtl,
    const float* __restrict__ ginv,
    __nv_bfloat16* __restrict__ xh, __nv_bfloat16* __restrict__ xl)
{
    const int t = blockIdx.x;              // 0..511, heavy bm first
    const int bm = 15 - (t >> 5);
    const int bh = t & 31;
    extern __shared__ char dsm[];
    const uint32_t sbase = smem_u32(dsm);
    const int b = bh / HH, h = bh % HH;
    const int tid  = threadIdx.x;
    const int lane = tid & 31;
    const int wid  = tid >> 5;
    const int wm   = wid >> 1;
    const int wn   = wid & 1;

    const size_t aoff = (size_t)bh * SS * SS + (size_t)(bm * 128) * SS;
    const size_t boff = (size_t)bh * DK * SS;

    MmaB16v6 core;
    core.run(sbase, eh + aoff, el + aoff, SS, vth + boff, vtl + boff, SS,
             (bm + 1) * 8, tid);

    #pragma unroll
    for (int mt = 0; mt < 4; mt++) {
        const int row = bm * 128 + wm * 64 + mt * 16 + (lane >> 2);
        const float inv0 = ginv[(size_t)bh * SS + row];
        const float inv1 = ginv[(size_t)bh * SS + row + 8];
        #pragma unroll
        for (int nt = 0; nt < 8; nt++) {
            const int col = wn * 64 + nt * 8 + (lane & 3) * 2;
            const float v0 = core.acc[mt][nt][0] * inv0;
            const float v1 = core.acc[mt][nt][1] * inv0;
            const float v2 = core.acc[mt][nt][2] * inv1;
            const float v3 = core.acc[mt][nt][3] * inv1;
            __nv_bfloat16 h0 = __float2bfloat16_rn(v0);
            __nv_bfloat16 h1 = __float2bfloat16_rn(v1);
            __nv_bfloat16 h2 = __float2bfloat16_rn(v2);
            __nv_bfloat16 h3 = __float2bfloat16_rn(v3);
            const size_t o0 = (size_t)(b * SS + row) * DD + h * DK + col;
            const size_t o1 = (size_t)(b * SS + row + 8) * DD + h * DK + col;
            *(uint32_t*)(xh + o0) = pack_bf2(h0, h1);
            *(uint32_t*)(xl + o0) = pack_bf2(
                __float2bfloat16_rn(v0 - __bfloat162float(h0)),
                __float2bfloat16_rn(v1 - __bfloat162float(h1)));
            *(uint32_t*)(xh + o1) = pack_bf2(h2, h3);
            *(uint32_t*)(xl + o1) = pack_bf2(
                __float2bfloat16_rn(v2 - __bfloat162float(h2)),
                __float2bfloat16_rn(v3 - __bfloat162float(h3)));
        }
    }
}

// ---------------------------------------------------------------------------
extern "C" void kernel_launch(void* const* d_in, const int* in_sizes, int n_in,
                              void* d_out, int out_size)
{
    const float* query = (const float*)d_in[0];
    const float* key   = (const float*)d_in[1];
    const float* value = (const float*)d_in[2];
    const float* Wq = (const float*)d_in[3];
    const float* bq = (const float*)d_in[4];
    const float* Wk = (const float*)d_in[5];
    const float* bk = (const float*)d_in[6];
    const float* Wv = (const float*)d_in[7];
    const float* bv = (const float*)d_in[8];
    const float* Wo = (const float*)d_in[9];
    const float* bo = (const float*)d_in[10];

    float* out  = (float*)d_out;                       // [4096, 2048]
    float* attn = out + (size_t)MTOK * DD;             // [32, 2048, 2048]

    float *v, *rpart, *ginv;
    __nv_bfloat16 *qih, *qil, *kih, *kil, *vih, *vil, *wh, *wl;
    __nv_bfloat16 *qh, *ql, *kh, *kl, *xh, *xl, *vth, *vtl, *eh, *el;
    cudaGetSymbolAddress((void**)&v, g_v);
    cudaGetSymbolAddress((void**)&rpart, g_rpart);
    cudaGetSymbolAddress((void**)&ginv, g_inv);
    cudaGetSymbolAddress((void**)&qih, g_qih);
    cudaGetSymbolAddress((void**)&qil, g_qil);
    cudaGetSymbolAddress((void**)&kih, g_kih);
    cudaGetSymbolAddress((void**)&kil, g_kil);
    cudaGetSymbolAddress((void**)&vih, g_vih);
    cudaGetSymbolAddress((void**)&vil, g_vil);
    cudaGetSymbolAddress((void**)&wh, g_wh);
    cudaGetSymbolAddress((void**)&wl, g_wl);
    cudaGetSymbolAddress((void**)&qh, g_qh);
    cudaGetSymbolAddress((void**)&ql, g_ql);
    cudaGetSymbolAddress((void**)&kh, g_kh);
    cudaGetSymbolAddress((void**)&kl, g_kl);
    cudaGetSymbolAddress((void**)&xh, g_xh);
    cudaGetSymbolAddress((void**)&xl, g_xl);
    cudaGetSymbolAddress((void**)&vth, g_vth);
    cudaGetSymbolAddress((void**)&vtl, g_vtl);
    cudaGetSymbolAddress((void**)&eh, g_eh);
    cudaGetSymbolAddress((void**)&el, g_el);

    static cudaStream_t s1 = nullptr;
    static cudaEvent_t evA = nullptr, evB = nullptr, evF = nullptr;
    static cudaEvent_t evP = nullptr, evT = nullptr;
    if (s1 == nullptr) {
        cudaStreamCreateWithFlags(&s1, cudaStreamNonBlocking);
        cudaEventCreateWithFlags(&evA, cudaEventDisableTiming);
        cudaEventCreateWithFlags(&evB, cudaEventDisableTiming);
        cudaEventCreateWithFlags(&evF, cudaEventDisableTiming);
        cudaEventCreateWithFlags(&evP, cudaEventDisableTiming);
        cudaEventCreateWithFlags(&evT, cudaEventDisableTiming);
        cudaFuncSetAttribute(proj_qkv,
            cudaFuncAttributeMaxDynamicSharedMemorySize, DSMEM_V6);
        cudaFuncSetAttribute(gemm_b16,
            cudaFuncAttributeMaxDynamicSharedMemorySize, DSMEM_V6);
        cudaFuncSetAttribute(scores_exp_kernel,
            cudaFuncAttributeMaxDynamicSharedMemorySize, DSMEM_V6);
        cudaFuncSetAttribute(av_mma_kernel,
            cudaFuncAttributeMaxDynamicSharedMemorySize, DSMEM_V6);
    }

    // Fork side stream: zero the above-diagonal attn tail (no dependencies)
    cudaEventRecord(evA, 0);
    cudaStreamWaitEvent(s1, evA, 0);
    zero_tail<<<BB * HH * SS, 256, 0, s1>>>(attn);

    // Main stream: splits -> proj
    dim3 gsi((MTOK * DD) / (256 * 4), 3);
    split_inputs<<<gsi, 256>>>(query, key, value,
                               qih, qil, kih, kil, vih, vil);
    dim3 gsw((DD * DD) / (256 * 4), 4);
    split_weights<<<gsw, 256>>>(Wq, Wk, Wv, Wo, wh, wl);

    dim3 gproj(DD / 128, MTOK / 128, 3);                // (16, 32, 3)
    proj_qkv<<<gproj, 128, DSMEM_V6>>>(
        qih, qil, kih, kil, vih, vil, wh, wl, bq, bk, bv,
        qh, ql, kh, kl, v);

    // Side stream: V transpose (scores doesn't need it; AV does)
    cudaEventRecord(evP, 0);
    cudaStreamWaitEvent(s1, evP, 0);
    dim3 gtr(SS / 32, DK / 32, BB * HH);
    transpose_v<<<gtr, 256, 0, s1>>>(v, vth, vtl);
    cudaEventRecord(evT, s1);

    // Main stream: scores -> ginv
    dim3 gsc(136, BB * HH);
    scores_exp_kernel<<<gsc, 128, DSMEM_V6>>>(qh, ql, kh, kl, eh, el, rpart);

    ginv_kernel<<<(BB * HH * SS) / 256, 256>>>(rpart, ginv);

    // Side stream: finalize attn prefix (overlaps AV + output projection)
    cudaEventRecord(evB, 0);
    cudaStreamWaitEvent(s1, evB, 0);
    finalize_prefix<<<BB * HH * SS, 256, 0, s1>>>(eh, el, ginv, attn);
    cudaEventRecord(evF, s1);

    // Main stream: AV (needs vt from side stream), output projection
    cudaStreamWaitEvent(0, evT, 0);
    av_mma_kernel<<<512, 128, DSMEM_V6>>>(eh, el, vth, vtl, ginv, xh, xl);

    dim3 gout(DD / 128, MTOK / 128);                    // (16, 32)
    gemm_b16<<<gout, 128, DSMEM_V6>>>(
        xh, xl, wh + (size_t)3 * DD * DD, wl + (size_t)3 * DD * DD, bo, out);

    // Join side stream into the graph
    cudaStreamWaitEvent(0, evF, 0);
}